// round 1
// baseline (speedup 1.0000x reference)
#include <cuda_runtime.h>
#include <math.h>

// Problem constants
#define Bc   2
#define Cc   64
#define Hc   192
#define Wc   192
#define Gc   4
#define Cgc  16
#define Kc   9
#define OC_OFF 18    // 2*K
#define OC_MOD 36    // G*K
#define HW   (Hc*Wc)

#define X_ELEMS   ((size_t)Bc*Cc*HW)        // 4,718,592
#define OFF_ELEMS ((size_t)Bc*72*HW)        // 5,308,416

// Scratch for modulator (no allocations allowed)
__device__ float g_modulator[(size_t)Bc*OC_MOD*HW];

// ---------------------------------------------------------------------------
// Kernel 1: offset conv. Per (b,g): conv3x3 over 32 in-ch (16 warp_ref group
// channels, then 16 source group channels), 18 out-ch, pad=1.
// Epilogue: 100*sigmoid(v)-50, written to offset_map section of d_out.
// ---------------------------------------------------------------------------
__global__ __launch_bounds__(256) void offset_conv_kernel(
    const float* __restrict__ wr, const float* __restrict__ src,
    const float* __restrict__ ow, const float* __restrict__ ob,
    float* __restrict__ out_off)
{
    __shared__ float s_in[16 * 10 * 34];   // chunk channels with halo
    __shared__ float s_w[16 * 9 * OC_OFF]; // [(c*9+k)*18 + o]

    const int tid = threadIdx.x;
    const int tx = tid & 31, ty = tid >> 5;
    const int x0 = blockIdx.x * 32, y0 = blockIdx.y * 8;
    const int bz = blockIdx.z;
    const int g = bz & 3, b = bz >> 2;

    float acc[OC_OFF];
#pragma unroll
    for (int o = 0; o < OC_OFF; o++) acc[o] = 0.f;

    for (int chunk = 0; chunk < 2; chunk++) {
        const float* base = (chunk == 0 ? wr : src) + ((size_t)(b * Cc + g * Cgc)) * HW;
        // input tile with halo
        for (int i = tid; i < 16 * 340; i += 256) {
            int c = i / 340, r = i % 340;
            int iy = r / 34, ix = r % 34;
            int gy = y0 - 1 + iy, gx = x0 - 1 + ix;
            float v = 0.f;
            if (gy >= 0 && gy < Hc && gx >= 0 && gx < Wc)
                v = base[(size_t)c * HW + gy * Wc + gx];
            s_in[i] = v;
        }
        // weights for this chunk
        for (int i = tid; i < 16 * 9 * OC_OFF; i += 256) {
            int o = i % OC_OFF;
            int ck = i / OC_OFF;
            int k = ck % 9, c = ck / 9;
            s_w[i] = ow[(o * 32 + chunk * 16 + c) * 9 + k];
        }
        __syncthreads();

#pragma unroll 2
        for (int c = 0; c < 16; c++) {
#pragma unroll
            for (int kh = 0; kh < 3; kh++) {
#pragma unroll
                for (int kw = 0; kw < 3; kw++) {
                    float v = s_in[c * 340 + (ty + kh) * 34 + (tx + kw)];
                    const float* wp = &s_w[(c * 9 + kh * 3 + kw) * OC_OFF];
#pragma unroll
                    for (int o = 0; o < OC_OFF; o++) acc[o] += v * wp[o];
                }
            }
        }
        __syncthreads();
    }

    const int x = x0 + tx, y = y0 + ty;
#pragma unroll
    for (int o = 0; o < OC_OFF; o++) {
        float v = acc[o] + ob[o];
        v = 100.f / (1.f + expf(-v)) - 50.f;
        out_off[((size_t)(b * 72 + g * OC_OFF + o) * Hc + y) * Wc + x] = v;
    }
}

// ---------------------------------------------------------------------------
// Kernel 2: modulator conv. conv3x3, I=64, O=36, pad=1, epi 2*sigmoid.
// ---------------------------------------------------------------------------
__global__ __launch_bounds__(256) void mod_conv_kernel(
    const float* __restrict__ wr,
    const float* __restrict__ mw, const float* __restrict__ mb,
    float* __restrict__ modout)
{
    __shared__ float s_in[16 * 10 * 34];
    __shared__ float s_w[16 * 9 * OC_MOD];

    const int tid = threadIdx.x;
    const int tx = tid & 31, ty = tid >> 5;
    const int x0 = blockIdx.x * 32, y0 = blockIdx.y * 8;
    const int b = blockIdx.z;

    float acc[OC_MOD];
#pragma unroll
    for (int o = 0; o < OC_MOD; o++) acc[o] = 0.f;

    for (int chunk = 0; chunk < 4; chunk++) {
        const float* base = wr + ((size_t)(b * Cc + chunk * 16)) * HW;
        for (int i = tid; i < 16 * 340; i += 256) {
            int c = i / 340, r = i % 340;
            int iy = r / 34, ix = r % 34;
            int gy = y0 - 1 + iy, gx = x0 - 1 + ix;
            float v = 0.f;
            if (gy >= 0 && gy < Hc && gx >= 0 && gx < Wc)
                v = base[(size_t)c * HW + gy * Wc + gx];
            s_in[i] = v;
        }
        for (int i = tid; i < 16 * 9 * OC_MOD; i += 256) {
            int o = i % OC_MOD;
            int ck = i / OC_MOD;
            int k = ck % 9, c = ck / 9;
            s_w[i] = mw[(o * Cc + chunk * 16 + c) * 9 + k];
        }
        __syncthreads();

#pragma unroll 2
        for (int c = 0; c < 16; c++) {
#pragma unroll
            for (int kh = 0; kh < 3; kh++) {
#pragma unroll
                for (int kw = 0; kw < 3; kw++) {
                    float v = s_in[c * 340 + (ty + kh) * 34 + (tx + kw)];
                    const float* wp = &s_w[(c * 9 + kh * 3 + kw) * OC_MOD];
#pragma unroll
                    for (int o = 0; o < OC_MOD; o++) acc[o] += v * wp[o];
                }
            }
        }
        __syncthreads();
    }

    const int x = x0 + tx, y = y0 + ty;
#pragma unroll
    for (int o = 0; o < OC_MOD; o++) {
        float v = acc[o] + mb[o];
        v = 2.f / (1.f + expf(-v));
        modout[((size_t)(b * OC_MOD + o) * Hc + y) * Wc + x] = v;
    }
}

// ---------------------------------------------------------------------------
// Kernel 3: modulated deformable conv.
// One thread = one output pixel, all 64 output channels in registers.
// Per-group weight tile in SMEM laid out [k][c][o] (o contiguous -> LDS.128).
// ---------------------------------------------------------------------------
__global__ __launch_bounds__(256) void deform_kernel(
    const float* __restrict__ wr,
    const float* __restrict__ off,   // [B,72,H,W] in d_out tail
    const float* __restrict__ mod,   // [B,36,H,W]
    const float* __restrict__ weight,// [64,64,3,3]
    float* __restrict__ out_x)
{
    __shared__ float s_w[9 * 16 * 64]; // [(k*16+c)*64 + o]

    const int tid = threadIdx.x;
    const int tx = tid & 31, ty = tid >> 5;
    const int x = blockIdx.x * 32 + tx;
    const int y = blockIdx.y * 8 + ty;
    const int b = blockIdx.z;

    float acc[64];
#pragma unroll
    for (int o = 0; o < 64; o++) acc[o] = 0.f;

    for (int g = 0; g < Gc; g++) {
        __syncthreads();
        for (int i = tid; i < 9216; i += 256) {
            int o = i & 63;
            int ck = i >> 6;
            int c = ck & 15, k = ck >> 4;
            s_w[i] = weight[(o * Cc + g * Cgc + c) * 9 + k];
        }
        __syncthreads();

        const float* base = wr + ((size_t)(b * Cc + g * Cgc)) * HW;

#pragma unroll 1
        for (int k = 0; k < 9; k++) {
            const int kh = k / 3, kw = k % 3;
            float oy = off[((size_t)(b * 72 + g * OC_OFF + 2 * k) * Hc + y) * Wc + x];
            float ox = off[((size_t)(b * 72 + g * OC_OFF + 2 * k + 1) * Hc + y) * Wc + x];
            float m  = mod[((size_t)(b * OC_MOD + g * 9 + k) * Hc + y) * Wc + x];

            float py = oy + (float)kh + (float)(y - 1);
            float px = ox + (float)kw + (float)(x - 1);
            float fy = floorf(py), fx = floorf(px);
            float ly = py - fy, lx = px - fx;
            int y0 = (int)fy, x0i = (int)fx;
            int y1 = y0 + 1, x1 = x0i + 1;

            float vy0 = (y0 >= 0 && y0 < Hc) ? 1.f : 0.f;
            float vy1 = (y1 >= 0 && y1 < Hc) ? 1.f : 0.f;
            float vx0 = (x0i >= 0 && x0i < Wc) ? 1.f : 0.f;
            float vx1 = (x1 >= 0 && x1 < Wc) ? 1.f : 0.f;

            int cy0 = min(max(y0, 0), Hc - 1), cy1 = min(max(y1, 0), Hc - 1);
            int cx0 = min(max(x0i, 0), Wc - 1), cx1 = min(max(x1, 0), Wc - 1);

            float w00 = (1.f - ly) * (1.f - lx) * m * vy0 * vx0;
            float w01 = (1.f - ly) * lx * m * vy0 * vx1;
            float w10 = ly * (1.f - lx) * m * vy1 * vx0;
            float w11 = ly * lx * m * vy1 * vx1;

            int i00 = cy0 * Wc + cx0, i01 = cy0 * Wc + cx1;
            int i10 = cy1 * Wc + cx0, i11 = cy1 * Wc + cx1;

            const float4* wk = reinterpret_cast<const float4*>(&s_w[k * 1024]);
#pragma unroll 2
            for (int c = 0; c < 16; c++) {
                const float* pl = base + (size_t)c * HW;
                float v = w00 * pl[i00] + w01 * pl[i01] + w10 * pl[i10] + w11 * pl[i11];
                const float4* wv = wk + c * 16;
#pragma unroll
                for (int o4 = 0; o4 < 16; o4++) {
                    float4 w4 = wv[o4];
                    acc[o4 * 4 + 0] += v * w4.x;
                    acc[o4 * 4 + 1] += v * w4.y;
                    acc[o4 * 4 + 2] += v * w4.z;
                    acc[o4 * 4 + 3] += v * w4.w;
                }
            }
        }
    }

#pragma unroll
    for (int o = 0; o < 64; o++)
        out_x[((size_t)(b * Cc + o) * Hc + y) * Wc + x] = acc[o];
}

// ---------------------------------------------------------------------------
extern "C" void kernel_launch(void* const* d_in, const int* in_sizes, int n_in,
                              void* d_out, int out_size)
{
    const float* warp_ref = (const float*)d_in[0];
    const float* source   = (const float*)d_in[1];
    const float* offset_w = (const float*)d_in[2];
    const float* offset_b = (const float*)d_in[3];
    const float* mod_w    = (const float*)d_in[4];
    const float* mod_b    = (const float*)d_in[5];
    const float* reg_w    = (const float*)d_in[6];

    float* out_x   = (float*)d_out;             // [B,64,H,W]
    float* out_off = (float*)d_out + X_ELEMS;   // [B,72,H,W]

    float* mod_scratch;
    cudaGetSymbolAddress((void**)&mod_scratch, g_modulator);

    dim3 blk(256);
    dim3 grid_off(Wc / 32, Hc / 8, Bc * Gc);
    dim3 grid_mod(Wc / 32, Hc / 8, Bc);
    dim3 grid_def(Wc / 32, Hc / 8, Bc);

    offset_conv_kernel<<<grid_off, blk>>>(warp_ref, source, offset_w, offset_b, out_off);
    mod_conv_kernel<<<grid_mod, blk>>>(warp_ref, mod_w, mod_b, mod_scratch);
    deform_kernel<<<grid_def, blk>>>(warp_ref, out_off, mod_scratch, reg_w, out_x);
}

// round 2
// speedup vs baseline: 1.2163x; 1.2163x over previous
#include <cuda_runtime.h>
#include <math.h>

#define Bc   2
#define Cc   64
#define Hc   192
#define Wc   192
#define Gc   4
#define Cgc  16
#define HW   (Hc*Wc)

#define X_ELEMS   ((size_t)Bc*Cc*HW)
typedef unsigned long long ull;

// Scratch (no allocations allowed)
__device__ float g_modulator[(size_t)Bc*36*HW];
__device__ float g_wt[4*9*16*64];     // weights re-laid [g][k][c][o]

// ---- f32x2 packed-FMA helpers -------------------------------------------
__device__ __forceinline__ ull ffma2(ull a, ull b, ull c) {
    ull d;
    asm("fma.rn.f32x2 %0, %1, %2, %3;" : "=l"(d) : "l"(a), "l"(b), "l"(c));
    return d;
}
__device__ __forceinline__ ull pack2(float lo, float hi) {
    ull r;
    asm("mov.b64 %0, {%1, %2};" : "=l"(r) : "f"(lo), "f"(hi));
    return r;
}
__device__ __forceinline__ float2 unpack2(ull v) {
    float2 f;
    asm("mov.b64 {%0, %1}, %2;" : "=f"(f.x), "=f"(f.y) : "l"(v));
    return f;
}
__device__ __forceinline__ float sigmoidf_(float v) {
    return 1.f / (1.f + expf(-v));
}

// ---------------------------------------------------------------------------
// Kernel 0: weight transform  reg_w[o][ic][kh][kw] -> g_wt[(g*9+k)*16+c][o]
// ---------------------------------------------------------------------------
__global__ void wt_transform_kernel(const float* __restrict__ w, float* __restrict__ wt)
{
    int i = blockIdx.x * 256 + threadIdx.x;   // 36864 total
    int o = i & 63;
    int r = i >> 6;
    int c = r & 15;
    int r2 = r >> 4;
    int k = r2 % 9, g = r2 / 9;
    wt[i] = w[(o * 64 + g * 16 + c) * 9 + k];
}

// ---------------------------------------------------------------------------
// Kernel 1: offset conv. Per (b,g): 3x3 conv, 32 in-ch, 18 out-ch, pad=1.
// 32x32 spatial tile, 4 pixels/thread, FFMA2 over 9 output-channel pairs.
// ---------------------------------------------------------------------------
__global__ __launch_bounds__(256) void offset_conv_kernel(
    const float* __restrict__ wr, const float* __restrict__ src,
    const float* __restrict__ ow, const float* __restrict__ ob,
    float* __restrict__ out_off)
{
    __shared__ float s_in[8 * 34 * 34];   // 9248
    __shared__ float s_w[8 * 9 * 20];     // rows padded to 20 floats (16B align)

    const int tid = threadIdx.x;
    const int tx = tid & 31, ty = tid >> 5;          // ty 0..7
    const int x0 = blockIdx.x * 32, y0 = blockIdx.y * 32;
    const int bz = blockIdx.z;
    const int g = bz & 3, b = bz >> 2;

    ull acc[4][9];
#pragma unroll
    for (int p = 0; p < 4; p++)
#pragma unroll
        for (int j = 0; j < 9; j++) acc[p][j] = 0ull;

#pragma unroll 1
    for (int chunk = 0; chunk < 4; chunk++) {
        const float* base = (chunk < 2 ? wr : src)
                          + ((size_t)(b * Cc + g * Cgc + (chunk & 1) * 8)) * HW;
        for (int i = tid; i < 9248; i += 256) {
            int c = i / 1156, r = i % 1156;
            int iy = r / 34, ix = r % 34;
            int gy = y0 - 1 + iy, gx = x0 - 1 + ix;
            float v = 0.f;
            if (gy >= 0 && gy < Hc && gx >= 0 && gx < Wc)
                v = base[(size_t)c * HW + gy * Wc + gx];
            s_in[i] = v;
        }
        for (int i = tid; i < 1440; i += 256) {
            int o = i % 20;
            int ck = i / 20;
            int k = ck % 9, c = ck / 9;
            s_w[i] = (o < 18) ? ow[(o * 32 + chunk * 8 + c) * 9 + k] : 0.f;
        }
        __syncthreads();

#pragma unroll 2
        for (int c = 0; c < 8; c++) {
#pragma unroll
            for (int t = 0; t < 9; t++) {
                const int kh = t / 3, kw = t % 3;
                const float* wrow = &s_w[(c * 9 + t) * 20];
                ulonglong2 l0 = *(const ulonglong2*)(wrow);
                ulonglong2 l1 = *(const ulonglong2*)(wrow + 4);
                ulonglong2 l2 = *(const ulonglong2*)(wrow + 8);
                ulonglong2 l3 = *(const ulonglong2*)(wrow + 12);
                ull w8 = *(const ull*)(wrow + 16);
#pragma unroll
                for (int p = 0; p < 4; p++) {
                    float v = s_in[c * 1156 + (ty + p * 8 + kh) * 34 + tx + kw];
                    ull vv = pack2(v, v);
                    acc[p][0] = ffma2(vv, l0.x, acc[p][0]);
                    acc[p][1] = ffma2(vv, l0.y, acc[p][1]);
                    acc[p][2] = ffma2(vv, l1.x, acc[p][2]);
                    acc[p][3] = ffma2(vv, l1.y, acc[p][3]);
                    acc[p][4] = ffma2(vv, l2.x, acc[p][4]);
                    acc[p][5] = ffma2(vv, l2.y, acc[p][5]);
                    acc[p][6] = ffma2(vv, l3.x, acc[p][6]);
                    acc[p][7] = ffma2(vv, l3.y, acc[p][7]);
                    acc[p][8] = ffma2(vv, w8,  acc[p][8]);
                }
            }
        }
        __syncthreads();
    }

    const int x = x0 + tx;
#pragma unroll
    for (int p = 0; p < 4; p++) {
        int y = y0 + ty + p * 8;
#pragma unroll
        for (int j = 0; j < 9; j++) {
            float2 f = unpack2(acc[p][j]);
            int o0 = 2 * j, o1 = 2 * j + 1;
            float v0 = 100.f * sigmoidf_(f.x + ob[o0]) - 50.f;
            float v1 = 100.f * sigmoidf_(f.y + ob[o1]) - 50.f;
            out_off[((size_t)(b * 72 + g * 18 + o0) * Hc + y) * Wc + x] = v0;
            out_off[((size_t)(b * 72 + g * 18 + o1) * Hc + y) * Wc + x] = v1;
        }
    }
}

// ---------------------------------------------------------------------------
// Kernel 2: modulator conv. 3x3, 64 in, 36 out, pad=1, epi 2*sigmoid.
// 32x16 spatial tile; thread = 4 pixels x 18 outs (o-half), FFMA2 pairs.
// ---------------------------------------------------------------------------
__global__ __launch_bounds__(256) void mod_conv_kernel(
    const float* __restrict__ wr,
    const float* __restrict__ mw, const float* __restrict__ mb,
    float* __restrict__ modout)
{
    __shared__ float s_in[8 * 18 * 34];   // 4896
    __shared__ float s_w[8 * 9 * 2 * 20]; // 2880

    const int tid = threadIdx.x;
    const int tx = tid & 31;
    const int q = tid >> 5;
    const int ty = q & 3;           // 0..3
    const int oh = q >> 2;          // 0/1
    const int x0 = blockIdx.x * 32, y0 = blockIdx.y * 16;
    const int b = blockIdx.z;

    ull acc[4][9];
#pragma unroll
    for (int p = 0; p < 4; p++)
#pragma unroll
        for (int j = 0; j < 9; j++) acc[p][j] = 0ull;

#pragma unroll 1
    for (int chunk = 0; chunk < 8; chunk++) {
        const float* base = wr + ((size_t)(b * Cc + chunk * 8)) * HW;
        for (int i = tid; i < 4896; i += 256) {
            int c = i / 612, r = i % 612;
            int iy = r / 34, ix = r % 34;
            int gy = y0 - 1 + iy, gx = x0 - 1 + ix;
            float v = 0.f;
            if (gy >= 0 && gy < Hc && gx >= 0 && gx < Wc)
                v = base[(size_t)c * HW + gy * Wc + gx];
            s_in[i] = v;
        }
        for (int i = tid; i < 2880; i += 256) {
            int o = i % 20;
            int rr = i / 20;
            int h = rr & 1;
            int ck = rr >> 1;
            int k = ck % 9, c = ck / 9;
            s_w[i] = (o < 18) ? mw[((h * 18 + o) * 64 + chunk * 8 + c) * 9 + k] : 0.f;
        }
        __syncthreads();

#pragma unroll 2
        for (int c = 0; c < 8; c++) {
#pragma unroll
            for (int t = 0; t < 9; t++) {
                const int kh = t / 3, kw = t % 3;
                const float* wrow = &s_w[((c * 9 + t) * 2 + oh) * 20];
                ulonglong2 l0 = *(const ulonglong2*)(wrow);
                ulonglong2 l1 = *(const ulonglong2*)(wrow + 4);
                ulonglong2 l2 = *(const ulonglong2*)(wrow + 8);
                ulonglong2 l3 = *(const ulonglong2*)(wrow + 12);
                ull w8 = *(const ull*)(wrow + 16);
#pragma unroll
                for (int p = 0; p < 4; p++) {
                    float v = s_in[c * 612 + (ty + p * 4 + kh) * 34 + tx + kw];
                    ull vv = pack2(v, v);
                    acc[p][0] = ffma2(vv, l0.x, acc[p][0]);
                    acc[p][1] = ffma2(vv, l0.y, acc[p][1]);
                    acc[p][2] = ffma2(vv, l1.x, acc[p][2]);
                    acc[p][3] = ffma2(vv, l1.y, acc[p][3]);
                    acc[p][4] = ffma2(vv, l2.x, acc[p][4]);
                    acc[p][5] = ffma2(vv, l2.y, acc[p][5]);
                    acc[p][6] = ffma2(vv, l3.x, acc[p][6]);
                    acc[p][7] = ffma2(vv, l3.y, acc[p][7]);
                    acc[p][8] = ffma2(vv, w8,  acc[p][8]);
                }
            }
        }
        __syncthreads();
    }

    const int x = x0 + tx;
#pragma unroll
    for (int p = 0; p < 4; p++) {
        int y = y0 + ty + p * 4;
#pragma unroll
        for (int j = 0; j < 9; j++) {
            float2 f = unpack2(acc[p][j]);
            int o0 = oh * 18 + 2 * j, o1 = o0 + 1;
            float v0 = 2.f * sigmoidf_(f.x + mb[o0]);
            float v1 = 2.f * sigmoidf_(f.y + mb[o1]);
            modout[((size_t)(b * 36 + o0) * Hc + y) * Wc + x] = v0;
            modout[((size_t)(b * 36 + o1) * Hc + y) * Wc + x] = v1;
        }
    }
}

// ---------------------------------------------------------------------------
// Kernel 3: deformable conv, staged-GEMM with double-buffered SMEM val tile.
// Block = 256 px (32x8). Per (g,k): gather bilinear vals -> s_val[16][256],
// stage weights (coalesced from g_wt) -> s_wk[16][64], then 8px x 8o
// register-tiled FFMA2 GEMM over c=16.
// ---------------------------------------------------------------------------
__global__ __launch_bounds__(256) void deform_kernel(
    const float* __restrict__ wr,
    const float* __restrict__ off,   // [B,72,H,W]
    const float* __restrict__ mod,   // [B,36,H,W]
    const float* __restrict__ gwt,   // [4*9*16, 64]
    float* __restrict__ out_x)
{
    __shared__ float s_val[2][16 * 256];
    __shared__ float s_wk[2][16 * 64];

    const int tid = threadIdx.x;
    const int tpx = tid & 31;     // pixel group
    const int to = tid >> 5;      // output-channel group (0..7)
    const int x0 = blockIdx.x * 32, y0 = blockIdx.y * 8;
    const int b = blockIdx.z;
    const int xg = x0 + (tid & 31);
    const int yg = y0 + (tid >> 5);

    ull acc[8][4];
#pragma unroll
    for (int p = 0; p < 8; p++)
#pragma unroll
        for (int j = 0; j < 4; j++) acc[p][j] = 0ull;

    auto gather = [&](int i) {
        const int g2 = i / 9, k2 = i % 9;
        const int bufi = i & 1;
        // stage weights (coalesced float4)
        *(float4*)&s_wk[bufi][tid * 4] = *(const float4*)&gwt[i * 1024 + tid * 4];
        // bilinear gather for this block's 256 pixels
        const int kh = k2 / 3, kw = k2 % 3;
        float oy = off[((size_t)(b * 72 + g2 * 18 + 2 * k2) * Hc + yg) * Wc + xg];
        float ox = off[((size_t)(b * 72 + g2 * 18 + 2 * k2 + 1) * Hc + yg) * Wc + xg];
        float m  = mod[((size_t)(b * 36 + g2 * 9 + k2) * Hc + yg) * Wc + xg];

        float py = oy + (float)kh + (float)(yg - 1);
        float px = ox + (float)kw + (float)(xg - 1);
        float fy = floorf(py), fx = floorf(px);
        float ly = py - fy, lx = px - fx;
        int iy0 = (int)fy, ix0 = (int)fx;
        int iy1 = iy0 + 1, ix1 = ix0 + 1;

        float vy0 = (iy0 >= 0 && iy0 < Hc) ? 1.f : 0.f;
        float vy1 = (iy1 >= 0 && iy1 < Hc) ? 1.f : 0.f;
        float vx0 = (ix0 >= 0 && ix0 < Wc) ? 1.f : 0.f;
        float vx1 = (ix1 >= 0 && ix1 < Wc) ? 1.f : 0.f;

        int cy0 = min(max(iy0, 0), Hc - 1), cy1 = min(max(iy1, 0), Hc - 1);
        int cx0 = min(max(ix0, 0), Wc - 1), cx1 = min(max(ix1, 0), Wc - 1);

        float w00 = (1.f - ly) * (1.f - lx) * m * vy0 * vx0;
        float w01 = (1.f - ly) * lx * m * vy0 * vx1;
        float w10 = ly * (1.f - lx) * m * vy1 * vx0;
        float w11 = ly * lx * m * vy1 * vx1;

        int i00 = cy0 * Wc + cx0, i01 = cy0 * Wc + cx1;
        int i10 = cy1 * Wc + cx0, i11 = cy1 * Wc + cx1;

        const float* base = wr + ((size_t)(b * Cc + g2 * Cgc)) * HW;
#pragma unroll
        for (int c = 0; c < 16; c++) {
            const float* pl = base + (size_t)c * HW;
            float v = w00 * pl[i00] + w01 * pl[i01] + w10 * pl[i10] + w11 * pl[i11];
            s_val[bufi][c * 256 + tid] = v;
        }
    };

    gather(0);

#pragma unroll 1
    for (int i = 0; i < 36; i++) {
        __syncthreads();
        if (i < 35) gather(i + 1);

        const float* vb_ = s_val[i & 1];
        const float* wb_ = s_wk[i & 1];
#pragma unroll
        for (int c = 0; c < 16; c++) {
            float4 va = *(const float4*)&vb_[c * 256 + tpx * 4];
            float4 vbv = *(const float4*)&vb_[c * 256 + 128 + tpx * 4];
            ulonglong2 wA = *(const ulonglong2*)&wb_[c * 64 + to * 4];
            ulonglong2 wB = *(const ulonglong2*)&wb_[c * 64 + 32 + to * 4];
            ull vv;
            vv = pack2(va.x, va.x);
            acc[0][0] = ffma2(vv, wA.x, acc[0][0]); acc[0][1] = ffma2(vv, wA.y, acc[0][1]);
            acc[0][2] = ffma2(vv, wB.x, acc[0][2]); acc[0][3] = ffma2(vv, wB.y, acc[0][3]);
            vv = pack2(va.y, va.y);
            acc[1][0] = ffma2(vv, wA.x, acc[1][0]); acc[1][1] = ffma2(vv, wA.y, acc[1][1]);
            acc[1][2] = ffma2(vv, wB.x, acc[1][2]); acc[1][3] = ffma2(vv, wB.y, acc[1][3]);
            vv = pack2(va.z, va.z);
            acc[2][0] = ffma2(vv, wA.x, acc[2][0]); acc[2][1] = ffma2(vv, wA.y, acc[2][1]);
            acc[2][2] = ffma2(vv, wB.x, acc[2][2]); acc[2][3] = ffma2(vv, wB.y, acc[2][3]);
            vv = pack2(va.w, va.w);
            acc[3][0] = ffma2(vv, wA.x, acc[3][0]); acc[3][1] = ffma2(vv, wA.y, acc[3][1]);
            acc[3][2] = ffma2(vv, wB.x, acc[3][2]); acc[3][3] = ffma2(vv, wB.y, acc[3][3]);
            vv = pack2(vbv.x, vbv.x);
            acc[4][0] = ffma2(vv, wA.x, acc[4][0]); acc[4][1] = ffma2(vv, wA.y, acc[4][1]);
            acc[4][2] = ffma2(vv, wB.x, acc[4][2]); acc[4][3] = ffma2(vv, wB.y, acc[4][3]);
            vv = pack2(vbv.y, vbv.y);
            acc[5][0] = ffma2(vv, wA.x, acc[5][0]); acc[5][1] = ffma2(vv, wA.y, acc[5][1]);
            acc[5][2] = ffma2(vv, wB.x, acc[5][2]); acc[5][3] = ffma2(vv, wB.y, acc[5][3]);
            vv = pack2(vbv.z, vbv.z);
            acc[6][0] = ffma2(vv, wA.x, acc[6][0]); acc[6][1] = ffma2(vv, wA.y, acc[6][1]);
            acc[6][2] = ffma2(vv, wB.x, acc[6][2]); acc[6][3] = ffma2(vv, wB.y, acc[6][3]);
            vv = pack2(vbv.w, vbv.w);
            acc[7][0] = ffma2(vv, wA.x, acc[7][0]); acc[7][1] = ffma2(vv, wA.y, acc[7][1]);
            acc[7][2] = ffma2(vv, wB.x, acc[7][2]); acc[7][3] = ffma2(vv, wB.y, acc[7][3]);
        }
    }

    // Store: px group A = tpx*4.. (rows 0-3), group B = 128+tpx*4.. (rows 4-7)
    const int yA = y0 + (tpx >> 3);
    const int yB = yA + 4;
    const int xA = x0 + ((tpx * 4) & 31);
#pragma unroll
    for (int qj = 0; qj < 4; qj++) {
        int o = (qj < 2) ? (to * 4 + 2 * qj) : (32 + to * 4 + 2 * (qj - 2));
        float2 f0 = unpack2(acc[0][qj]);
        float2 f1 = unpack2(acc[1][qj]);
        float2 f2 = unpack2(acc[2][qj]);
        float2 f3 = unpack2(acc[3][qj]);
        float4 lo = make_float4(f0.x, f1.x, f2.x, f3.x);
        float4 hi = make_float4(f0.y, f1.y, f2.y, f3.y);
        *(float4*)&out_x[((size_t)(b * Cc + o) * Hc + yA) * Wc + xA] = lo;
        *(float4*)&out_x[((size_t)(b * Cc + o + 1) * Hc + yA) * Wc + xA] = hi;
        float2 g0 = unpack2(acc[4][qj]);
        float2 g1 = unpack2(acc[5][qj]);
        float2 g2 = unpack2(acc[6][qj]);
        float2 g3 = unpack2(acc[7][qj]);
        float4 lo2 = make_float4(g0.x, g1.x, g2.x, g3.x);
        float4 hi2 = make_float4(g0.y, g1.y, g2.y, g3.y);
        *(float4*)&out_x[((size_t)(b * Cc + o) * Hc + yB) * Wc + xA] = lo2;
        *(float4*)&out_x[((size_t)(b * Cc + o + 1) * Hc + yB) * Wc + xA] = hi2;
    }
}

// ---------------------------------------------------------------------------
extern "C" void kernel_launch(void* const* d_in, const int* in_sizes, int n_in,
                              void* d_out, int out_size)
{
    const float* warp_ref = (const float*)d_in[0];
    const float* source   = (const float*)d_in[1];
    const float* offset_w = (const float*)d_in[2];
    const float* offset_b = (const float*)d_in[3];
    const float* mod_w    = (const float*)d_in[4];
    const float* mod_b    = (const float*)d_in[5];
    const float* reg_w    = (const float*)d_in[6];

    float* out_x   = (float*)d_out;             // [B,64,H,W]
    float* out_off = (float*)d_out + X_ELEMS;   // [B,72,H,W]

    float* mod_scratch;
    float* wt_scratch;
    cudaGetSymbolAddress((void**)&mod_scratch, g_modulator);
    cudaGetSymbolAddress((void**)&wt_scratch, g_wt);

    dim3 blk(256);
    wt_transform_kernel<<<144, blk>>>(reg_w, wt_scratch);
    offset_conv_kernel<<<dim3(6, 6, 8), blk>>>(warp_ref, source, offset_w, offset_b, out_off);
    mod_conv_kernel<<<dim3(6, 12, 2), blk>>>(warp_ref, mod_w, mod_b, mod_scratch);
    deform_kernel<<<dim3(6, 24, 2), blk>>>(warp_ref, out_off, mod_scratch, wt_scratch, out_x);
}

// round 3
// speedup vs baseline: 1.4668x; 1.2060x over previous
#include <cuda_runtime.h>
#include <math.h>
#include <stdint.h>

#define Bc   2
#define Cc   64
#define Hc   192
#define Wc   192
#define Gc   4
#define Cgc  16
#define HW   (Hc*Wc)
#define Nsz  (Bc*HW)          // 73728 pixels total

#define X_ELEMS   ((size_t)Bc*Cc*HW)
typedef unsigned long long ull;

// Scratch (no allocations allowed)
__device__ float g_modulator[(size_t)Bc*36*HW];
__device__ float g_wt[4*9*16*64];               // [ (g*9+k)*16+c ][ o ]
__device__ float g_nhwc[(size_t)Bc*HW*64];      // [b][p][c]
__device__ float g_vals[(size_t)576*Nsz];       // [ (g*9+k)*16+c ][ b*HW+p ]

// ---- helpers --------------------------------------------------------------
__device__ __forceinline__ ull ffma2(ull a, ull b, ull c) {
    ull d;
    asm("fma.rn.f32x2 %0, %1, %2, %3;" : "=l"(d) : "l"(a), "l"(b), "l"(c));
    return d;
}
__device__ __forceinline__ ull pack2(float lo, float hi) {
    ull r;
    asm("mov.b64 %0, {%1, %2};" : "=l"(r) : "f"(lo), "f"(hi));
    return r;
}
__device__ __forceinline__ float2 unpack2(ull v) {
    float2 f;
    asm("mov.b64 {%0, %1}, %2;" : "=f"(f.x), "=f"(f.y) : "l"(v));
    return f;
}
__device__ __forceinline__ float sigmoidf_(float v) {
    return 1.f / (1.f + expf(-v));
}
__device__ __forceinline__ void cp_async16(void* smem, const void* g) {
    uint32_t s = (uint32_t)__cvta_generic_to_shared(smem);
    asm volatile("cp.async.cg.shared.global [%0], [%1], 16;" :: "r"(s), "l"(g));
}
__device__ __forceinline__ float4 f4fma(float4 a, float s, float4 acc) {
    acc.x = fmaf(a.x, s, acc.x);
    acc.y = fmaf(a.y, s, acc.y);
    acc.z = fmaf(a.z, s, acc.z);
    acc.w = fmaf(a.w, s, acc.w);
    return acc;
}

// ---------------------------------------------------------------------------
// Kernel 0a: weight transform  reg_w[o][ic][kh][kw] -> g_wt[(g*9+k)*16+c][o]
// ---------------------------------------------------------------------------
__global__ void wt_transform_kernel(const float* __restrict__ w, float* __restrict__ wt)
{
    int i = blockIdx.x * 256 + threadIdx.x;   // 36864 total
    int o = i & 63;
    int r = i >> 6;
    int c = r & 15;
    int r2 = r >> 4;
    int k = r2 % 9, g = r2 / 9;
    wt[i] = w[(o * 64 + g * 16 + c) * 9 + k];
}

// ---------------------------------------------------------------------------
// Kernel 0b: NCHW -> NHWC transpose of warp_ref  ([B,64,HW] -> [B,HW,64])
// ---------------------------------------------------------------------------
__global__ __launch_bounds__(256) void nhwc_kernel(
    const float* __restrict__ in, float* __restrict__ outp)
{
    __shared__ float t[32][33];
    const int tx = threadIdx.x & 31, ty = threadIdx.x >> 5;
    const int p0 = blockIdx.x * 32;
    const int c0 = blockIdx.y * 32;
    const int b  = blockIdx.z;
#pragma unroll
    for (int j = 0; j < 4; j++) {
        int c = c0 + ty + j * 8;
        t[ty + j * 8][tx] = in[((size_t)(b * Cc + c)) * HW + p0 + tx];
    }
    __syncthreads();
#pragma unroll
    for (int j = 0; j < 4; j++) {
        int p = p0 + ty + j * 8;
        outp[((size_t)b * HW + p) * 64 + c0 + tx] = t[tx][ty + j * 8];
    }
}

// ---------------------------------------------------------------------------
// Kernel 1: offset conv (unchanged from R2)
// ---------------------------------------------------------------------------
__global__ __launch_bounds__(256) void offset_conv_kernel(
    const float* __restrict__ wr, const float* __restrict__ src,
    const float* __restrict__ ow, const float* __restrict__ ob,
    float* __restrict__ out_off)
{
    __shared__ float s_in[8 * 34 * 34];
    __shared__ float s_w[8 * 9 * 20];

    const int tid = threadIdx.x;
    const int tx = tid & 31, ty = tid >> 5;
    const int x0 = blockIdx.x * 32, y0 = blockIdx.y * 32;
    const int bz = blockIdx.z;
    const int g = bz & 3, b = bz >> 2;

    ull acc[4][9];
#pragma unroll
    for (int p = 0; p < 4; p++)
#pragma unroll
        for (int j = 0; j < 9; j++) acc[p][j] = 0ull;

#pragma unroll 1
    for (int chunk = 0; chunk < 4; chunk++) {
        const float* base = (chunk < 2 ? wr : src)
                          + ((size_t)(b * Cc + g * Cgc + (chunk & 1) * 8)) * HW;
        for (int i = tid; i < 9248; i += 256) {
            int c = i / 1156, r = i % 1156;
            int iy = r / 34, ix = r % 34;
            int gy = y0 - 1 + iy, gx = x0 - 1 + ix;
            float v = 0.f;
            if (gy >= 0 && gy < Hc && gx >= 0 && gx < Wc)
                v = base[(size_t)c * HW + gy * Wc + gx];
            s_in[i] = v;
        }
        for (int i = tid; i < 1440; i += 256) {
            int o = i % 20;
            int ck = i / 20;
            int k = ck % 9, c = ck / 9;
            s_w[i] = (o < 18) ? ow[(o * 32 + chunk * 8 + c) * 9 + k] : 0.f;
        }
        __syncthreads();

#pragma unroll 2
        for (int c = 0; c < 8; c++) {
#pragma unroll
            for (int t = 0; t < 9; t++) {
                const int kh = t / 3, kw = t % 3;
                const float* wrow = &s_w[(c * 9 + t) * 20];
                ulonglong2 l0 = *(const ulonglong2*)(wrow);
                ulonglong2 l1 = *(const ulonglong2*)(wrow + 4);
                ulonglong2 l2 = *(const ulonglong2*)(wrow + 8);
                ulonglong2 l3 = *(const ulonglong2*)(wrow + 12);
                ull w8 = *(const ull*)(wrow + 16);
#pragma unroll
                for (int p = 0; p < 4; p++) {
                    float v = s_in[c * 1156 + (ty + p * 8 + kh) * 34 + tx + kw];
                    ull vv = pack2(v, v);
                    acc[p][0] = ffma2(vv, l0.x, acc[p][0]);
                    acc[p][1] = ffma2(vv, l0.y, acc[p][1]);
                    acc[p][2] = ffma2(vv, l1.x, acc[p][2]);
                    acc[p][3] = ffma2(vv, l1.y, acc[p][3]);
                    acc[p][4] = ffma2(vv, l2.x, acc[p][4]);
                    acc[p][5] = ffma2(vv, l2.y, acc[p][5]);
                    acc[p][6] = ffma2(vv, l3.x, acc[p][6]);
                    acc[p][7] = ffma2(vv, l3.y, acc[p][7]);
                    acc[p][8] = ffma2(vv, w8,  acc[p][8]);
                }
            }
        }
        __syncthreads();
    }

    const int x = x0 + tx;
#pragma unroll
    for (int p = 0; p < 4; p++) {
        int y = y0 + ty + p * 8;
#pragma unroll
        for (int j = 0; j < 9; j++) {
            float2 f = unpack2(acc[p][j]);
            int o0 = 2 * j, o1 = 2 * j + 1;
            float v0 = 100.f * sigmoidf_(f.x + ob[o0]) - 50.f;
            float v1 = 100.f * sigmoidf_(f.y + ob[o1]) - 50.f;
            out_off[((size_t)(b * 72 + g * 18 + o0) * Hc + y) * Wc + x] = v0;
            out_off[((size_t)(b * 72 + g * 18 + o1) * Hc + y) * Wc + x] = v1;
        }
    }
}

// ---------------------------------------------------------------------------
// Kernel 2: modulator conv (unchanged from R2)
// ---------------------------------------------------------------------------
__global__ __launch_bounds__(256) void mod_conv_kernel(
    const float* __restrict__ wr,
    const float* __restrict__ mw, const float* __restrict__ mb,
    float* __restrict__ modout)
{
    __shared__ float s_in[8 * 18 * 34];
    __shared__ float s_w[8 * 9 * 2 * 20];

    const int tid = threadIdx.x;
    const int tx = tid & 31;
    const int q = tid >> 5;
    const int ty = q & 3;
    const int oh = q >> 2;
    const int x0 = blockIdx.x * 32, y0 = blockIdx.y * 16;
    const int b = blockIdx.z;

    ull acc[4][9];
#pragma unroll
    for (int p = 0; p < 4; p++)
#pragma unroll
        for (int j = 0; j < 9; j++) acc[p][j] = 0ull;

#pragma unroll 1
    for (int chunk = 0; chunk < 8; chunk++) {
        const float* base = wr + ((size_t)(b * Cc + chunk * 8)) * HW;
        for (int i = tid; i < 4896; i += 256) {
            int c = i / 612, r = i % 612;
            int iy = r / 34, ix = r % 34;
            int gy = y0 - 1 + iy, gx = x0 - 1 + ix;
            float v = 0.f;
            if (gy >= 0 && gy < Hc && gx >= 0 && gx < Wc)
                v = base[(size_t)c * HW + gy * Wc + gx];
            s_in[i] = v;
        }
        for (int i = tid; i < 2880; i += 256) {
            int o = i % 20;
            int rr = i / 20;
            int h = rr & 1;
            int ck = rr >> 1;
            int k = ck % 9, c = ck / 9;
            s_w[i] = (o < 18) ? mw[((h * 18 + o) * 64 + chunk * 8 + c) * 9 + k] : 0.f;
        }
        __syncthreads();

#pragma unroll 2
        for (int c = 0; c < 8; c++) {
#pragma unroll
            for (int t = 0; t < 9; t++) {
                const int kh = t / 3, kw = t % 3;
                const float* wrow = &s_w[((c * 9 + t) * 2 + oh) * 20];
                ulonglong2 l0 = *(const ulonglong2*)(wrow);
                ulonglong2 l1 = *(const ulonglong2*)(wrow + 4);
                ulonglong2 l2 = *(const ulonglong2*)(wrow + 8);
                ulonglong2 l3 = *(const ulonglong2*)(wrow + 12);
                ull w8 = *(const ull*)(wrow + 16);
#pragma unroll
                for (int p = 0; p < 4; p++) {
                    float v = s_in[c * 612 + (ty + p * 4 + kh) * 34 + tx + kw];
                    ull vv = pack2(v, v);
                    acc[p][0] = ffma2(vv, l0.x, acc[p][0]);
                    acc[p][1] = ffma2(vv, l0.y, acc[p][1]);
                    acc[p][2] = ffma2(vv, l1.x, acc[p][2]);
                    acc[p][3] = ffma2(vv, l1.y, acc[p][3]);
                    acc[p][4] = ffma2(vv, l2.x, acc[p][4]);
                    acc[p][5] = ffma2(vv, l2.y, acc[p][5]);
                    acc[p][6] = ffma2(vv, l3.x, acc[p][6]);
                    acc[p][7] = ffma2(vv, l3.y, acc[p][7]);
                    acc[p][8] = ffma2(vv, w8,  acc[p][8]);
                }
            }
        }
        __syncthreads();
    }

    const int x = x0 + tx;
#pragma unroll
    for (int p = 0; p < 4; p++) {
        int y = y0 + ty + p * 4;
#pragma unroll
        for (int j = 0; j < 9; j++) {
            float2 f = unpack2(acc[p][j]);
            int o0 = oh * 18 + 2 * j, o1 = o0 + 1;
            float v0 = 2.f * sigmoidf_(f.x + mb[o0]);
            float v1 = 2.f * sigmoidf_(f.y + mb[o1]);
            modout[((size_t)(b * 36 + o0) * Hc + y) * Wc + x] = v0;
            modout[((size_t)(b * 36 + o1) * Hc + y) * Wc + x] = v1;
        }
    }
}

// ---------------------------------------------------------------------------
// Kernel 3a: bilinear gather -> g_vals[576][Nsz]. NHWC input: one corner for
// a group = 16 contiguous floats = 4x LDG.128.
// ---------------------------------------------------------------------------
__global__ __launch_bounds__(256) void gather_kernel(
    const float* __restrict__ nhwc,
    const float* __restrict__ off,
    const float* __restrict__ mod,
    float* __restrict__ vals)
{
    const int p = blockIdx.x * 256 + threadIdx.x;
    const int b = blockIdx.y;
    const int yy = p / Wc, xx = p % Wc;
    const size_t col = (size_t)b * HW + p;
    const float* nb = nhwc + (size_t)b * HW * 64;

#pragma unroll 1
    for (int g = 0; g < 4; g++) {
#pragma unroll 1
        for (int k = 0; k < 9; k++) {
            const int kh = k / 3, kw = k % 3;
            float oy = off[((size_t)(b * 72 + g * 18 + 2 * k)) * HW + p];
            float ox = off[((size_t)(b * 72 + g * 18 + 2 * k + 1)) * HW + p];
            float m  = mod[((size_t)(b * 36 + g * 9 + k)) * HW + p];

            float py = oy + (float)kh + (float)(yy - 1);
            float px = ox + (float)kw + (float)(xx - 1);
            float fy = floorf(py), fx = floorf(px);
            float ly = py - fy, lx = px - fx;
            int iy0 = (int)fy, ix0 = (int)fx;
            int iy1 = iy0 + 1, ix1 = ix0 + 1;

            float vy0 = (iy0 >= 0 && iy0 < Hc) ? 1.f : 0.f;
            float vy1 = (iy1 >= 0 && iy1 < Hc) ? 1.f : 0.f;
            float vx0 = (ix0 >= 0 && ix0 < Wc) ? 1.f : 0.f;
            float vx1 = (ix1 >= 0 && ix1 < Wc) ? 1.f : 0.f;

            int cy0 = min(max(iy0, 0), Hc - 1), cy1 = min(max(iy1, 0), Hc - 1);
            int cx0 = min(max(ix0, 0), Wc - 1), cx1 = min(max(ix1, 0), Wc - 1);

            float w00 = (1.f - ly) * (1.f - lx) * m * vy0 * vx0;
            float w01 = (1.f - ly) * lx * m * vy0 * vx1;
            float w10 = ly * (1.f - lx) * m * vy1 * vx0;
            float w11 = ly * lx * m * vy1 * vx1;

            const float4* p00 = (const float4*)(nb + ((size_t)(cy0 * Wc + cx0)) * 64 + g * 16);
            const float4* p01 = (const float4*)(nb + ((size_t)(cy0 * Wc + cx1)) * 64 + g * 16);
            const float4* p10 = (const float4*)(nb + ((size_t)(cy1 * Wc + cx0)) * 64 + g * 16);
            const float4* p11 = (const float4*)(nb + ((size_t)(cy1 * Wc + cx1)) * 64 + g * 16);

            float4 a[4];
#pragma unroll
            for (int q = 0; q < 4; q++) {
                float4 acc = make_float4(0.f, 0.f, 0.f, 0.f);
                acc = f4fma(p00[q], w00, acc);
                acc = f4fma(p01[q], w01, acc);
                acc = f4fma(p10[q], w10, acc);
                acc = f4fma(p11[q], w11, acc);
                a[q] = acc;
            }

            const size_t rbase = (size_t)((g * 9 + k) * 16);
            const float* af = (const float*)a;
#pragma unroll
            for (int c = 0; c < 16; c++)
                vals[(rbase + c) * (size_t)Nsz + col] = af[c];
        }
    }
}

// ---------------------------------------------------------------------------
// Kernel 3b: dense GEMM  out[64, Nsz] = g_wt^T[64,576] * g_vals[576, Nsz]
// cp.async double-buffered tiles: Bt[16][256] px, At[16][64] outs.
// Thread: 8 px x 8 outs, FFMA2.
// ---------------------------------------------------------------------------
__global__ __launch_bounds__(256) void gemm_kernel(
    const float* __restrict__ vals,
    const float* __restrict__ gwt,
    float* __restrict__ out_x)
{
    __shared__ float Bt[2][16 * 256];
    __shared__ float At[2][16 * 64];

    const int tid = threadIdx.x;
    const int tpx = tid & 31;
    const int to = tid >> 5;
    const size_t col0 = (size_t)blockIdx.x * 256;
    const int b = blockIdx.x / (HW / 256);
    const size_t p0 = col0 - (size_t)b * HW;

    auto stage = [&](int i) {
        const int buf = i & 1;
#pragma unroll
        for (int j = 0; j < 4; j++) {
            int flat = (tid + j * 256) * 4;
            int c = flat >> 8, o = flat & 255;
            cp_async16(&Bt[buf][c * 256 + o], &vals[((size_t)(i * 16 + c)) * Nsz + col0 + o]);
        }
        {
            int flat = tid * 4;
            int c = flat >> 6, o = flat & 63;
            cp_async16(&At[buf][c * 64 + o], &gwt[(i * 16 + c) * 64 + o]);
        }
        asm volatile("cp.async.commit_group;" ::: "memory");
    };

    ull acc[8][4];
#pragma unroll
    for (int p = 0; p < 8; p++)
#pragma unroll
        for (int j = 0; j < 4; j++) acc[p][j] = 0ull;

    stage(0);

#pragma unroll 1
    for (int i = 0; i < 36; i++) {
        asm volatile("cp.async.wait_group 0;" ::: "memory");
        __syncthreads();
        if (i < 35) stage(i + 1);

        const float* vb_ = Bt[i & 1];
        const float* wb_ = At[i & 1];
#pragma unroll
        for (int c = 0; c < 16; c++) {
            float4 va  = *(const float4*)&vb_[c * 256 + tpx * 4];
            float4 vbv = *(const float4*)&vb_[c * 256 + 128 + tpx * 4];
            ulonglong2 wA = *(const ulonglong2*)&wb_[c * 64 + to * 4];
            ulonglong2 wB = *(const ulonglong2*)&wb_[c * 64 + 32 + to * 4];
            ull vv;
            vv = pack2(va.x, va.x);
            acc[0][0] = ffma2(vv, wA.x, acc[0][0]); acc[0][1] = ffma2(vv, wA.y, acc[0][1]);
            acc[0][2] = ffma2(vv, wB.x, acc[0][2]); acc[0][3] = ffma2(vv, wB.y, acc[0][3]);
            vv = pack2(va.y, va.y);
            acc[1][0] = ffma2(vv, wA.x, acc[1][0]); acc[1][1] = ffma2(vv, wA.y, acc[1][1]);
            acc[1][2] = ffma2(vv, wB.x, acc[1][2]); acc[1][3] = ffma2(vv, wB.y, acc[1][3]);
            vv = pack2(va.z, va.z);
            acc[2][0] = ffma2(vv, wA.x, acc[2][0]); acc[2][1] = ffma2(vv, wA.y, acc[2][1]);
            acc[2][2] = ffma2(vv, wB.x, acc[2][2]); acc[2][3] = ffma2(vv, wB.y, acc[2][3]);
            vv = pack2(va.w, va.w);
            acc[3][0] = ffma2(vv, wA.x, acc[3][0]); acc[3][1] = ffma2(vv, wA.y, acc[3][1]);
            acc[3][2] = ffma2(vv, wB.x, acc[3][2]); acc[3][3] = ffma2(vv, wB.y, acc[3][3]);
            vv = pack2(vbv.x, vbv.x);
            acc[4][0] = ffma2(vv, wA.x, acc[4][0]); acc[4][1] = ffma2(vv, wA.y, acc[4][1]);
            acc[4][2] = ffma2(vv, wB.x, acc[4][2]); acc[4][3] = ffma2(vv, wB.y, acc[4][3]);
            vv = pack2(vbv.y, vbv.y);
            acc[5][0] = ffma2(vv, wA.x, acc[5][0]); acc[5][1] = ffma2(vv, wA.y, acc[5][1]);
            acc[5][2] = ffma2(vv, wB.x, acc[5][2]); acc[5][3] = ffma2(vv, wB.y, acc[5][3]);
            vv = pack2(vbv.z, vbv.z);
            acc[6][0] = ffma2(vv, wA.x, acc[6][0]); acc[6][1] = ffma2(vv, wA.y, acc[6][1]);
            acc[6][2] = ffma2(vv, wB.x, acc[6][2]); acc[6][3] = ffma2(vv, wB.y, acc[6][3]);
            vv = pack2(vbv.w, vbv.w);
            acc[7][0] = ffma2(vv, wA.x, acc[7][0]); acc[7][1] = ffma2(vv, wA.y, acc[7][1]);
            acc[7][2] = ffma2(vv, wB.x, acc[7][2]); acc[7][3] = ffma2(vv, wB.y, acc[7][3]);
        }
    }

    // Epilogue: pixels are contiguous along p0.
#pragma unroll
    for (int qj = 0; qj < 4; qj++) {
        int o = (qj < 2) ? (to * 4 + 2 * qj) : (32 + to * 4 + 2 * (qj - 2));
        float2 f0 = unpack2(acc[0][qj]);
        float2 f1 = unpack2(acc[1][qj]);
        float2 f2 = unpack2(acc[2][qj]);
        float2 f3 = unpack2(acc[3][qj]);
        float4 lo = make_float4(f0.x, f1.x, f2.x, f3.x);
        float4 hi = make_float4(f0.y, f1.y, f2.y, f3.y);
        *(float4*)&out_x[((size_t)(b * Cc + o)) * HW + p0 + tpx * 4] = lo;
        *(float4*)&out_x[((size_t)(b * Cc + o + 1)) * HW + p0 + tpx * 4] = hi;
        float2 g0 = unpack2(acc[4][qj]);
        float2 g1 = unpack2(acc[5][qj]);
        float2 g2 = unpack2(acc[6][qj]);
        float2 g3 = unpack2(acc[7][qj]);
        float4 lo2 = make_float4(g0.x, g1.x, g2.x, g3.x);
        float4 hi2 = make_float4(g0.y, g1.y, g2.y, g3.y);
        *(float4*)&out_x[((size_t)(b * Cc + o)) * HW + p0 + 128 + tpx * 4] = lo2;
        *(float4*)&out_x[((size_t)(b * Cc + o + 1)) * HW + p0 + 128 + tpx * 4] = hi2;
    }
}

// ---------------------------------------------------------------------------
extern "C" void kernel_launch(void* const* d_in, const int* in_sizes, int n_in,
                              void* d_out, int out_size)
{
    const float* warp_ref = (const float*)d_in[0];
    const float* source   = (const float*)d_in[1];
    const float* offset_w = (const float*)d_in[2];
    const float* offset_b = (const float*)d_in[3];
    const float* mod_w    = (const float*)d_in[4];
    const float* mod_b    = (const float*)d_in[5];
    const float* reg_w    = (const float*)d_in[6];

    float* out_x   = (float*)d_out;             // [B,64,H,W]
    float* out_off = (float*)d_out + X_ELEMS;   // [B,72,H,W]

    float *mod_scratch, *wt_scratch, *nhwc_scratch, *vals_scratch;
    cudaGetSymbolAddress((void**)&mod_scratch, g_modulator);
    cudaGetSymbolAddress((void**)&wt_scratch, g_wt);
    cudaGetSymbolAddress((void**)&nhwc_scratch, g_nhwc);
    cudaGetSymbolAddress((void**)&vals_scratch, g_vals);

    dim3 blk(256);
    wt_transform_kernel<<<144, blk>>>(reg_w, wt_scratch);
    nhwc_kernel<<<dim3(HW / 32, 2, Bc), blk>>>(warp_ref, nhwc_scratch);
    offset_conv_kernel<<<dim3(6, 6, 8), blk>>>(warp_ref, source, offset_w, offset_b, out_off);
    mod_conv_kernel<<<dim3(6, 12, 2), blk>>>(warp_ref, mod_w, mod_b, mod_scratch);
    gather_kernel<<<dim3(HW / 256, Bc), blk>>>(nhwc_scratch, out_off, mod_scratch, vals_scratch);
    gemm_kernel<<<dim3(Nsz / 256), blk>>>(vals_scratch, wt_scratch, out_x);
}

// round 4
// speedup vs baseline: 1.4733x; 1.0044x over previous
#include <cuda_runtime.h>
#include <math.h>
#include <stdint.h>

#define Bc   2
#define Cc   64
#define Hc   192
#define Wc   192
#define Gc   4
#define Cgc  16
#define HW   (Hc*Wc)
#define Nsz  (Bc*HW)          // 73728 pixels total

#define X_ELEMS   ((size_t)Bc*Cc*HW)
typedef unsigned long long ull;

// Scratch (no allocations allowed)
__device__ float g_modulator[(size_t)Bc*36*HW];
__device__ float g_wt[4*9*16*64];               // [ (g*9+k)*16+c ][ o ]
__device__ float g_nhwc[(size_t)Bc*HW*64];      // [b][p][c]
__device__ float g_vals[(size_t)576*Nsz];       // [ (g*9+k)*16+c ][ b*HW+p ]

// ---- helpers --------------------------------------------------------------
__device__ __forceinline__ ull ffma2(ull a, ull b, ull c) {
    ull d;
    asm("fma.rn.f32x2 %0, %1, %2, %3;" : "=l"(d) : "l"(a), "l"(b), "l"(c));
    return d;
}
__device__ __forceinline__ ull pack2(float lo, float hi) {
    ull r;
    asm("mov.b64 %0, {%1, %2};" : "=l"(r) : "f"(lo), "f"(hi));
    return r;
}
__device__ __forceinline__ float2 unpack2(ull v) {
    float2 f;
    asm("mov.b64 {%0, %1}, %2;" : "=f"(f.x), "=f"(f.y) : "l"(v));
    return f;
}
__device__ __forceinline__ float sigmoidf_(float v) {
    return 1.f / (1.f + expf(-v));
}
__device__ __forceinline__ void cp_async16(void* smem, const void* g) {
    uint32_t s = (uint32_t)__cvta_generic_to_shared(smem);
    asm volatile("cp.async.cg.shared.global [%0], [%1], 16;" :: "r"(s), "l"(g));
}
__device__ __forceinline__ float4 f4fma(float4 a, float s, float4 acc) {
    acc.x = fmaf(a.x, s, acc.x);
    acc.y = fmaf(a.y, s, acc.y);
    acc.z = fmaf(a.z, s, acc.z);
    acc.w = fmaf(a.w, s, acc.w);
    return acc;
}

// ---------------------------------------------------------------------------
// Kernel 0a: weight transform  reg_w[o][ic][kh][kw] -> g_wt[(g*9+k)*16+c][o]
// ---------------------------------------------------------------------------
__global__ void wt_transform_kernel(const float* __restrict__ w, float* __restrict__ wt)
{
    int i = blockIdx.x * 256 + threadIdx.x;   // 36864 total
    int o = i & 63;
    int r = i >> 6;
    int c = r & 15;
    int r2 = r >> 4;
    int k = r2 % 9, g = r2 / 9;
    wt[i] = w[(o * 64 + g * 16 + c) * 9 + k];
}

// ---------------------------------------------------------------------------
// Kernel 0b: NCHW -> NHWC transpose of warp_ref  ([B,64,HW] -> [B,HW,64])
// ---------------------------------------------------------------------------
__global__ __launch_bounds__(256) void nhwc_kernel(
    const float* __restrict__ in, float* __restrict__ outp)
{
    __shared__ float t[32][33];
    const int tx = threadIdx.x & 31, ty = threadIdx.x >> 5;
    const int p0 = blockIdx.x * 32;
    const int c0 = blockIdx.y * 32;
    const int b  = blockIdx.z;
#pragma unroll
    for (int j = 0; j < 4; j++) {
        int c = c0 + ty + j * 8;
        t[ty + j * 8][tx] = in[((size_t)(b * Cc + c)) * HW + p0 + tx];
    }
    __syncthreads();
#pragma unroll
    for (int j = 0; j < 4; j++) {
        int p = p0 + ty + j * 8;
        outp[((size_t)b * HW + p) * 64 + c0 + tx] = t[tx][ty + j * 8];
    }
}

// ---------------------------------------------------------------------------
// Kernel 1: offset conv. Per (b,g): 3x3 conv, 32 in-ch, 18 out-ch, pad=1.
// 32x16 tile, 2 px/thread, grid 576 for occupancy.
// ---------------------------------------------------------------------------
__global__ __launch_bounds__(256) void offset_conv_kernel(
    const float* __restrict__ wr, const float* __restrict__ src,
    const float* __restrict__ ow, const float* __restrict__ ob,
    float* __restrict__ out_off)
{
    __shared__ float s_in[8 * 18 * 34];   // 4896
    __shared__ float s_w[8 * 9 * 20];     // 1440

    const int tid = threadIdx.x;
    const int tx = tid & 31, ty = tid >> 5;          // ty 0..7
    const int x0 = blockIdx.x * 32, y0 = blockIdx.y * 16;
    const int bz = blockIdx.z;
    const int g = bz & 3, b = bz >> 2;

    ull acc[2][9];
#pragma unroll
    for (int p = 0; p < 2; p++)
#pragma unroll
        for (int j = 0; j < 9; j++) acc[p][j] = 0ull;

#pragma unroll 1
    for (int chunk = 0; chunk < 4; chunk++) {
        const float* base = (chunk < 2 ? wr : src)
                          + ((size_t)(b * Cc + g * Cgc + (chunk & 1) * 8)) * HW;
        for (int i = tid; i < 4896; i += 256) {
            int c = i / 612, r = i % 612;
            int iy = r / 34, ix = r % 34;
            int gy = y0 - 1 + iy, gx = x0 - 1 + ix;
            float v = 0.f;
            if (gy >= 0 && gy < Hc && gx >= 0 && gx < Wc)
                v = base[(size_t)c * HW + gy * Wc + gx];
            s_in[i] = v;
        }
        for (int i = tid; i < 1440; i += 256) {
            int o = i % 20;
            int ck = i / 20;
            int k = ck % 9, c = ck / 9;
            s_w[i] = (o < 18) ? ow[(o * 32 + chunk * 8 + c) * 9 + k] : 0.f;
        }
        __syncthreads();

#pragma unroll 2
        for (int c = 0; c < 8; c++) {
#pragma unroll
            for (int t = 0; t < 9; t++) {
                const int kh = t / 3, kw = t % 3;
                const float* wrow = &s_w[(c * 9 + t) * 20];
                ulonglong2 l0 = *(const ulonglong2*)(wrow);
                ulonglong2 l1 = *(const ulonglong2*)(wrow + 4);
                ulonglong2 l2 = *(const ulonglong2*)(wrow + 8);
                ulonglong2 l3 = *(const ulonglong2*)(wrow + 12);
                ull w8 = *(const ull*)(wrow + 16);
#pragma unroll
                for (int p = 0; p < 2; p++) {
                    float v = s_in[c * 612 + (ty + p * 8 + kh) * 34 + tx + kw];
                    ull vv = pack2(v, v);
                    acc[p][0] = ffma2(vv, l0.x, acc[p][0]);
                    acc[p][1] = ffma2(vv, l0.y, acc[p][1]);
                    acc[p][2] = ffma2(vv, l1.x, acc[p][2]);
                    acc[p][3] = ffma2(vv, l1.y, acc[p][3]);
                    acc[p][4] = ffma2(vv, l2.x, acc[p][4]);
                    acc[p][5] = ffma2(vv, l2.y, acc[p][5]);
                    acc[p][6] = ffma2(vv, l3.x, acc[p][6]);
                    acc[p][7] = ffma2(vv, l3.y, acc[p][7]);
                    acc[p][8] = ffma2(vv, w8,  acc[p][8]);
                }
            }
        }
        __syncthreads();
    }

    const int x = x0 + tx;
#pragma unroll
    for (int p = 0; p < 2; p++) {
        int y = y0 + ty + p * 8;
#pragma unroll
        for (int j = 0; j < 9; j++) {
            float2 f = unpack2(acc[p][j]);
            int o0 = 2 * j, o1 = 2 * j + 1;
            float v0 = 100.f * sigmoidf_(f.x + ob[o0]) - 50.f;
            float v1 = 100.f * sigmoidf_(f.y + ob[o1]) - 50.f;
            out_off[((size_t)(b * 72 + g * 18 + o0) * Hc + y) * Wc + x] = v0;
            out_off[((size_t)(b * 72 + g * 18 + o1) * Hc + y) * Wc + x] = v1;
        }
    }
}

// ---------------------------------------------------------------------------
// Kernel 2: modulator conv. 3x3, 64 in, 36 out, pad=1, epi 2*sigmoid.
// 32x8 tile, 2 px/thread x 18 outs (o-half), grid 288 for occupancy.
// ---------------------------------------------------------------------------
__global__ __launch_bounds__(256) void mod_conv_kernel(
    const float* __restrict__ wr,
    const float* __restrict__ mw, const float* __restrict__ mb,
    float* __restrict__ modout)
{
    __shared__ float s_in[8 * 10 * 34];   // 2720
    __shared__ float s_w[8 * 9 * 2 * 20]; // 2880

    const int tid = threadIdx.x;
    const int tx = tid & 31;
    const int q = tid >> 5;
    const int ty = q & 3;           // 0..3
    const int oh = q >> 2;          // 0/1
    const int x0 = blockIdx.x * 32, y0 = blockIdx.y * 8;
    const int b = blockIdx.z;

    ull acc[2][9];
#pragma unroll
    for (int p = 0; p < 2; p++)
#pragma unroll
        for (int j = 0; j < 9; j++) acc[p][j] = 0ull;

#pragma unroll 1
    for (int chunk = 0; chunk < 8; chunk++) {
        const float* base = wr + ((size_t)(b * Cc + chunk * 8)) * HW;
        for (int i = tid; i < 2720; i += 256) {
            int c = i / 340, r = i % 340;
            int iy = r / 34, ix = r % 34;
            int gy = y0 - 1 + iy, gx = x0 - 1 + ix;
            float v = 0.f;
            if (gy >= 0 && gy < Hc && gx >= 0 && gx < Wc)
                v = base[(size_t)c * HW + gy * Wc + gx];
            s_in[i] = v;
        }
        for (int i = tid; i < 2880; i += 256) {
            int o = i % 20;
            int rr = i / 20;
            int h = rr & 1;
            int ck = rr >> 1;
            int k = ck % 9, c = ck / 9;
            s_w[i] = (o < 18) ? mw[((h * 18 + o) * 64 + chunk * 8 + c) * 9 + k] : 0.f;
        }
        __syncthreads();

#pragma unroll 2
        for (int c = 0; c < 8; c++) {
#pragma unroll
            for (int t = 0; t < 9; t++) {
                const int kh = t / 3, kw = t % 3;
                const float* wrow = &s_w[((c * 9 + t) * 2 + oh) * 20];
                ulonglong2 l0 = *(const ulonglong2*)(wrow);
                ulonglong2 l1 = *(const ulonglong2*)(wrow + 4);
                ulonglong2 l2 = *(const ulonglong2*)(wrow + 8);
                ulonglong2 l3 = *(const ulonglong2*)(wrow + 12);
                ull w8 = *(const ull*)(wrow + 16);
#pragma unroll
                for (int p = 0; p < 2; p++) {
                    float v = s_in[c * 340 + (ty + p * 4 + kh) * 34 + tx + kw];
                    ull vv = pack2(v, v);
                    acc[p][0] = ffma2(vv, l0.x, acc[p][0]);
                    acc[p][1] = ffma2(vv, l0.y, acc[p][1]);
                    acc[p][2] = ffma2(vv, l1.x, acc[p][2]);
                    acc[p][3] = ffma2(vv, l1.y, acc[p][3]);
                    acc[p][4] = ffma2(vv, l2.x, acc[p][4]);
                    acc[p][5] = ffma2(vv, l2.y, acc[p][5]);
                    acc[p][6] = ffma2(vv, l3.x, acc[p][6]);
                    acc[p][7] = ffma2(vv, l3.y, acc[p][7]);
                    acc[p][8] = ffma2(vv, w8,  acc[p][8]);
                }
            }
        }
        __syncthreads();
    }

    const int x = x0 + tx;
#pragma unroll
    for (int p = 0; p < 2; p++) {
        int y = y0 + ty + p * 4;
#pragma unroll
        for (int j = 0; j < 9; j++) {
            float2 f = unpack2(acc[p][j]);
            int o0 = oh * 18 + 2 * j, o1 = o0 + 1;
            float v0 = 2.f * sigmoidf_(f.x + mb[o0]);
            float v1 = 2.f * sigmoidf_(f.y + mb[o1]);
            modout[((size_t)(b * 36 + o0) * Hc + y) * Wc + x] = v0;
            modout[((size_t)(b * 36 + o1) * Hc + y) * Wc + x] = v1;
        }
    }
}

// ---------------------------------------------------------------------------
// Kernel 3a: bilinear gather -> g_vals[576][Nsz]. NHWC input: one corner for
// a group = 16 contiguous floats = 4x LDG.128.
// ---------------------------------------------------------------------------
__global__ __launch_bounds__(256) void gather_kernel(
    const float* __restrict__ nhwc,
    const float* __restrict__ off,
    const float* __restrict__ mod,
    float* __restrict__ vals)
{
    const int p = blockIdx.x * 256 + threadIdx.x;
    const int b = blockIdx.y;
    const int yy = p / Wc, xx = p % Wc;
    const size_t col = (size_t)b * HW + p;
    const float* nb = nhwc + (size_t)b * HW * 64;

#pragma unroll 1
    for (int g = 0; g < 4; g++) {
#pragma unroll 1
        for (int k = 0; k < 9; k++) {
            const int kh = k / 3, kw = k % 3;
            float oy = off[((size_t)(b * 72 + g * 18 + 2 * k)) * HW + p];
            float ox = off[((size_t)(b * 72 + g * 18 + 2 * k + 1)) * HW + p];
            float m  = mod[((size_t)(b * 36 + g * 9 + k)) * HW + p];

            float py = oy + (float)kh + (float)(yy - 1);
            float px = ox + (float)kw + (float)(xx - 1);
            float fy = floorf(py), fx = floorf(px);
            float ly = py - fy, lx = px - fx;
            int iy0 = (int)fy, ix0 = (int)fx;
            int iy1 = iy0 + 1, ix1 = ix0 + 1;

            float vy0 = (iy0 >= 0 && iy0 < Hc) ? 1.f : 0.f;
            float vy1 = (iy1 >= 0 && iy1 < Hc) ? 1.f : 0.f;
            float vx0 = (ix0 >= 0 && ix0 < Wc) ? 1.f : 0.f;
            float vx1 = (ix1 >= 0 && ix1 < Wc) ? 1.f : 0.f;

            int cy0 = min(max(iy0, 0), Hc - 1), cy1 = min(max(iy1, 0), Hc - 1);
            int cx0 = min(max(ix0, 0), Wc - 1), cx1 = min(max(ix1, 0), Wc - 1);

            float w00 = (1.f - ly) * (1.f - lx) * m * vy0 * vx0;
            float w01 = (1.f - ly) * lx * m * vy0 * vx1;
            float w10 = ly * (1.f - lx) * m * vy1 * vx0;
            float w11 = ly * lx * m * vy1 * vx1;

            const float4* p00 = (const float4*)(nb + ((size_t)(cy0 * Wc + cx0)) * 64 + g * 16);
            const float4* p01 = (const float4*)(nb + ((size_t)(cy0 * Wc + cx1)) * 64 + g * 16);
            const float4* p10 = (const float4*)(nb + ((size_t)(cy1 * Wc + cx0)) * 64 + g * 16);
            const float4* p11 = (const float4*)(nb + ((size_t)(cy1 * Wc + cx1)) * 64 + g * 16);

            float4 a[4];
#pragma unroll
            for (int q = 0; q < 4; q++) {
                float4 acc = make_float4(0.f, 0.f, 0.f, 0.f);
                acc = f4fma(p00[q], w00, acc);
                acc = f4fma(p01[q], w01, acc);
                acc = f4fma(p10[q], w10, acc);
                acc = f4fma(p11[q], w11, acc);
                a[q] = acc;
            }

            const size_t rbase = (size_t)((g * 9 + k) * 16);
            const float* af = (const float*)a;
#pragma unroll
            for (int c = 0; c < 16; c++)
                vals[(rbase + c) * (size_t)Nsz + col] = af[c];
        }
    }
}

// ---------------------------------------------------------------------------
// Kernel 3b: dense GEMM  out[64, Nsz] = g_wt^T[64,576] * g_vals[576, Nsz]
// cp.async double-buffered tiles: Bt[16][256] px, At[16][64] outs.
// Thread: 8 px x 8 outs, FFMA2.
// ---------------------------------------------------------------------------
__global__ __launch_bounds__(256) void gemm_kernel(
    const float* __restrict__ vals,
    const float* __restrict__ gwt,
    float* __restrict__ out_x)
{
    __shared__ float Bt[2][16 * 256];
    __shared__ float At[2][16 * 64];

    const int tid = threadIdx.x;
    const int tpx = tid & 31;
    const int to = tid >> 5;
    const size_t col0 = (size_t)blockIdx.x * 256;
    const int b = blockIdx.x / (HW / 256);
    const size_t p0 = col0 - (size_t)b * HW;

    auto stage = [&](int i) {
        const int buf = i & 1;
#pragma unroll
        for (int j = 0; j < 4; j++) {
            int flat = (tid + j * 256) * 4;
            int c = flat >> 8, o = flat & 255;
            cp_async16(&Bt[buf][c * 256 + o], &vals[((size_t)(i * 16 + c)) * Nsz + col0 + o]);
        }
        {
            int flat = tid * 4;
            int c = flat >> 6, o = flat & 63;
            cp_async16(&At[buf][c * 64 + o], &gwt[(i * 16 + c) * 64 + o]);
        }
        asm volatile("cp.async.commit_group;" ::: "memory");
    };

    ull acc[8][4];
#pragma unroll
    for (int p = 0; p < 8; p++)
#pragma unroll
        for (int j = 0; j < 4; j++) acc[p][j] = 0ull;

    stage(0);

#pragma unroll 1
    for (int i = 0; i < 36; i++) {
        asm volatile("cp.async.wait_group 0;" ::: "memory");
        __syncthreads();
        if (i < 35) stage(i + 1);

        const float* vb_ = Bt[i & 1];
        const float* wb_ = At[i & 1];
#pragma unroll
        for (int c = 0; c < 16; c++) {
            float4 va  = *(const float4*)&vb_[c * 256 + tpx * 4];
            float4 vbv = *(const float4*)&vb_[c * 256 + 128 + tpx * 4];
            ulonglong2 wA = *(const ulonglong2*)&wb_[c * 64 + to * 4];
            ulonglong2 wB = *(const ulonglong2*)&wb_[c * 64 + 32 + to * 4];
            ull vv;
            vv = pack2(va.x, va.x);
            acc[0][0] = ffma2(vv, wA.x, acc[0][0]); acc[0][1] = ffma2(vv, wA.y, acc[0][1]);
            acc[0][2] = ffma2(vv, wB.x, acc[0][2]); acc[0][3] = ffma2(vv, wB.y, acc[0][3]);
            vv = pack2(va.y, va.y);
            acc[1][0] = ffma2(vv, wA.x, acc[1][0]); acc[1][1] = ffma2(vv, wA.y, acc[1][1]);
            acc[1][2] = ffma2(vv, wB.x, acc[1][2]); acc[1][3] = ffma2(vv, wB.y, acc[1][3]);
            vv = pack2(va.z, va.z);
            acc[2][0] = ffma2(vv, wA.x, acc[2][0]); acc[2][1] = ffma2(vv, wA.y, acc[2][1]);
            acc[2][2] = ffma2(vv, wB.x, acc[2][2]); acc[2][3] = ffma2(vv, wB.y, acc[2][3]);
            vv = pack2(va.w, va.w);
            acc[3][0] = ffma2(vv, wA.x, acc[3][0]); acc[3][1] = ffma2(vv, wA.y, acc[3][1]);
            acc[3][2] = ffma2(vv, wB.x, acc[3][2]); acc[3][3] = ffma2(vv, wB.y, acc[3][3]);
            vv = pack2(vbv.x, vbv.x);
            acc[4][0] = ffma2(vv, wA.x, acc[4][0]); acc[4][1] = ffma2(vv, wA.y, acc[4][1]);
            acc[4][2] = ffma2(vv, wB.x, acc[4][2]); acc[4][3] = ffma2(vv, wB.y, acc[4][3]);
            vv = pack2(vbv.y, vbv.y);
            acc[5][0] = ffma2(vv, wA.x, acc[5][0]); acc[5][1] = ffma2(vv, wA.y, acc[5][1]);
            acc[5][2] = ffma2(vv, wB.x, acc[5][2]); acc[5][3] = ffma2(vv, wB.y, acc[5][3]);
            vv = pack2(vbv.z, vbv.z);
            acc[6][0] = ffma2(vv, wA.x, acc[6][0]); acc[6][1] = ffma2(vv, wA.y, acc[6][1]);
            acc[6][2] = ffma2(vv, wB.x, acc[6][2]); acc[6][3] = ffma2(vv, wB.y, acc[6][3]);
            vv = pack2(vbv.w, vbv.w);
            acc[7][0] = ffma2(vv, wA.x, acc[7][0]); acc[7][1] = ffma2(vv, wA.y, acc[7][1]);
            acc[7][2] = ffma2(vv, wB.x, acc[7][2]); acc[7][3] = ffma2(vv, wB.y, acc[7][3]);
        }
    }

    // Epilogue: pixels are contiguous along p0.
#pragma unroll
    for (int qj = 0; qj < 4; qj++) {
        int o = (qj < 2) ? (to * 4 + 2 * qj) : (32 + to * 4 + 2 * (qj - 2));
        float2 f0 = unpack2(acc[0][qj]);
        float2 f1 = unpack2(acc[1][qj]);
        float2 f2 = unpack2(acc[2][qj]);
        float2 f3 = unpack2(acc[3][qj]);
        float4 lo = make_float4(f0.x, f1.x, f2.x, f3.x);
        float4 hi = make_float4(f0.y, f1.y, f2.y, f3.y);
        *(float4*)&out_x[((size_t)(b * Cc + o)) * HW + p0 + tpx * 4] = lo;
        *(float4*)&out_x[((size_t)(b * Cc + o + 1)) * HW + p0 + tpx * 4] = hi;
        float2 g0 = unpack2(acc[4][qj]);
        float2 g1 = unpack2(acc[5][qj]);
        float2 g2 = unpack2(acc[6][qj]);
        float2 g3 = unpack2(acc[7][qj]);
        float4 lo2 = make_float4(g0.x, g1.x, g2.x, g3.x);
        float4 hi2 = make_float4(g0.y, g1.y, g2.y, g3.y);
        *(float4*)&out_x[((size_t)(b * Cc + o)) * HW + p0 + 128 + tpx * 4] = lo2;
        *(float4*)&out_x[((size_t)(b * Cc + o + 1)) * HW + p0 + 128 + tpx * 4] = hi2;
    }
}

// ---------------------------------------------------------------------------
extern "C" void kernel_launch(void* const* d_in, const int* in_sizes, int n_in,
                              void* d_out, int out_size)
{
    const float* warp_ref = (const float*)d_in[0];
    const float* source   = (const float*)d_in[1];
    const float* offset_w = (const float*)d_in[2];
    const float* offset_b = (const float*)d_in[3];
    const float* mod_w    = (const float*)d_in[4];
    const float* mod_b    = (const float*)d_in[5];
    const float* reg_w    = (const float*)d_in[6];

    float* out_x   = (float*)d_out;             // [B,64,H,W]
    float* out_off = (float*)d_out + X_ELEMS;   // [B,72,H,W]

    float *mod_scratch, *wt_scratch, *nhwc_scratch, *vals_scratch;
    cudaGetSymbolAddress((void**)&mod_scratch, g_modulator);
    cudaGetSymbolAddress((void**)&wt_scratch, g_wt);
    cudaGetSymbolAddress((void**)&nhwc_scratch, g_nhwc);
    cudaGetSymbolAddress((void**)&vals_scratch, g_vals);

    dim3 blk(256);
    wt_transform_kernel<<<144, blk>>>(reg_w, wt_scratch);
    nhwc_kernel<<<dim3(HW / 32, 2, Bc), blk>>>(warp_ref, nhwc_scratch);
    offset_conv_kernel<<<dim3(6, 12, 8), blk>>>(warp_ref, source, offset_w, offset_b, out_off);
    mod_conv_kernel<<<dim3(6, 24, 2), blk>>>(warp_ref, mod_w, mod_b, mod_scratch);
    gather_kernel<<<dim3(HW / 256, Bc), blk>>>(nhwc_scratch, out_off, mod_scratch, vals_scratch);
    gemm_kernel<<<dim3(Nsz / 256), blk>>>(vals_scratch, wt_scratch, out_x);
}

// round 5
// speedup vs baseline: 1.6518x; 1.1212x over previous
#include <cuda_runtime.h>
#include <math.h>
#include <stdint.h>

#define Bc   2
#define Cc   64
#define Hc   192
#define Wc   192
#define Gc   4
#define Cgc  16
#define HW   (Hc*Wc)
#define Nsz  (Bc*HW)          // 73728 pixels total

#define X_ELEMS   ((size_t)Bc*Cc*HW)
typedef unsigned long long ull;

// Scratch (no allocations allowed)
__device__ float g_modulator[(size_t)Bc*36*HW];
__device__ float g_wt[4*9*16*64];               // [ (g*9+k)*16+c ][ o ]
__device__ float g_nhwc[(size_t)Bc*HW*64];      // [b][p][c]

// ---- helpers --------------------------------------------------------------
__device__ __forceinline__ ull ffma2(ull a, ull b, ull c) {
    ull d;
    asm("fma.rn.f32x2 %0, %1, %2, %3;" : "=l"(d) : "l"(a), "l"(b), "l"(c));
    return d;
}
__device__ __forceinline__ ull pack2(float lo, float hi) {
    ull r;
    asm("mov.b64 %0, {%1, %2};" : "=l"(r) : "f"(lo), "f"(hi));
    return r;
}
__device__ __forceinline__ float2 unpack2(ull v) {
    float2 f;
    asm("mov.b64 {%0, %1}, %2;" : "=f"(f.x), "=f"(f.y) : "l"(v));
    return f;
}
__device__ __forceinline__ float sigmoidf_(float v) {
    return 1.f / (1.f + expf(-v));
}
__device__ __forceinline__ void cp_async16(void* smem, const void* g) {
    uint32_t s = (uint32_t)__cvta_generic_to_shared(smem);
    asm volatile("cp.async.cg.shared.global [%0], [%1], 16;" :: "r"(s), "l"(g));
}

// ---------------------------------------------------------------------------
// Kernel 0a: weight transform  reg_w[o][ic][kh][kw] -> g_wt[(g*9+k)*16+c][o]
// ---------------------------------------------------------------------------
__global__ void wt_transform_kernel(const float* __restrict__ w, float* __restrict__ wt)
{
    int i = blockIdx.x * 256 + threadIdx.x;   // 36864 total
    int o = i & 63;
    int r = i >> 6;
    int c = r & 15;
    int r2 = r >> 4;
    int k = r2 % 9, g = r2 / 9;
    wt[i] = w[(o * 64 + g * 16 + c) * 9 + k];
}

// ---------------------------------------------------------------------------
// Kernel 0b: NCHW -> NHWC transpose of warp_ref  ([B,64,HW] -> [B,HW,64])
// ---------------------------------------------------------------------------
__global__ __launch_bounds__(256) void nhwc_kernel(
    const float* __restrict__ in, float* __restrict__ outp)
{
    __shared__ float t[32][33];
    const int tx = threadIdx.x & 31, ty = threadIdx.x >> 5;
    const int p0 = blockIdx.x * 32;
    const int c0 = blockIdx.y * 32;
    const int b  = blockIdx.z;
#pragma unroll
    for (int j = 0; j < 4; j++) {
        int c = c0 + ty + j * 8;
        t[ty + j * 8][tx] = in[((size_t)(b * Cc + c)) * HW + p0 + tx];
    }
    __syncthreads();
#pragma unroll
    for (int j = 0; j < 4; j++) {
        int p = p0 + ty + j * 8;
        outp[((size_t)b * HW + p) * 64 + c0 + tx] = t[tx][ty + j * 8];
    }
}

// ---------------------------------------------------------------------------
// Kernel 1: offset conv (unchanged from R4)
// ---------------------------------------------------------------------------
__global__ __launch_bounds__(256) void offset_conv_kernel(
    const float* __restrict__ wr, const float* __restrict__ src,
    const float* __restrict__ ow, const float* __restrict__ ob,
    float* __restrict__ out_off)
{
    __shared__ float s_in[8 * 18 * 34];   // 4896
    __shared__ float s_w[8 * 9 * 20];     // 1440

    const int tid = threadIdx.x;
    const int tx = tid & 31, ty = tid >> 5;
    const int x0 = blockIdx.x * 32, y0 = blockIdx.y * 16;
    const int bz = blockIdx.z;
    const int g = bz & 3, b = bz >> 2;

    ull acc[2][9];
#pragma unroll
    for (int p = 0; p < 2; p++)
#pragma unroll
        for (int j = 0; j < 9; j++) acc[p][j] = 0ull;

#pragma unroll 1
    for (int chunk = 0; chunk < 4; chunk++) {
        const float* base = (chunk < 2 ? wr : src)
                          + ((size_t)(b * Cc + g * Cgc + (chunk & 1) * 8)) * HW;
        for (int i = tid; i < 4896; i += 256) {
            int c = i / 612, r = i % 612;
            int iy = r / 34, ix = r % 34;
            int gy = y0 - 1 + iy, gx = x0 - 1 + ix;
            float v = 0.f;
            if (gy >= 0 && gy < Hc && gx >= 0 && gx < Wc)
                v = base[(size_t)c * HW + gy * Wc + gx];
            s_in[i] = v;
        }
        for (int i = tid; i < 1440; i += 256) {
            int o = i % 20;
            int ck = i / 20;
            int k = ck % 9, c = ck / 9;
            s_w[i] = (o < 18) ? ow[(o * 32 + chunk * 8 + c) * 9 + k] : 0.f;
        }
        __syncthreads();

#pragma unroll 2
        for (int c = 0; c < 8; c++) {
#pragma unroll
            for (int t = 0; t < 9; t++) {
                const int kh = t / 3, kw = t % 3;
                const float* wrow = &s_w[(c * 9 + t) * 20];
                ulonglong2 l0 = *(const ulonglong2*)(wrow);
                ulonglong2 l1 = *(const ulonglong2*)(wrow + 4);
                ulonglong2 l2 = *(const ulonglong2*)(wrow + 8);
                ulonglong2 l3 = *(const ulonglong2*)(wrow + 12);
                ull w8 = *(const ull*)(wrow + 16);
#pragma unroll
                for (int p = 0; p < 2; p++) {
                    float v = s_in[c * 612 + (ty + p * 8 + kh) * 34 + tx + kw];
                    ull vv = pack2(v, v);
                    acc[p][0] = ffma2(vv, l0.x, acc[p][0]);
                    acc[p][1] = ffma2(vv, l0.y, acc[p][1]);
                    acc[p][2] = ffma2(vv, l1.x, acc[p][2]);
                    acc[p][3] = ffma2(vv, l1.y, acc[p][3]);
                    acc[p][4] = ffma2(vv, l2.x, acc[p][4]);
                    acc[p][5] = ffma2(vv, l2.y, acc[p][5]);
                    acc[p][6] = ffma2(vv, l3.x, acc[p][6]);
                    acc[p][7] = ffma2(vv, l3.y, acc[p][7]);
                    acc[p][8] = ffma2(vv, w8,  acc[p][8]);
                }
            }
        }
        __syncthreads();
    }

    const int x = x0 + tx;
#pragma unroll
    for (int p = 0; p < 2; p++) {
        int y = y0 + ty + p * 8;
#pragma unroll
        for (int j = 0; j < 9; j++) {
            float2 f = unpack2(acc[p][j]);
            int o0 = 2 * j, o1 = 2 * j + 1;
            float v0 = 100.f * sigmoidf_(f.x + ob[o0]) - 50.f;
            float v1 = 100.f * sigmoidf_(f.y + ob[o1]) - 50.f;
            out_off[((size_t)(b * 72 + g * 18 + o0) * Hc + y) * Wc + x] = v0;
            out_off[((size_t)(b * 72 + g * 18 + o1) * Hc + y) * Wc + x] = v1;
        }
    }
}

// ---------------------------------------------------------------------------
// Kernel 2: modulator conv (unchanged from R4)
// ---------------------------------------------------------------------------
__global__ __launch_bounds__(256) void mod_conv_kernel(
    const float* __restrict__ wr,
    const float* __restrict__ mw, const float* __restrict__ mb,
    float* __restrict__ modout)
{
    __shared__ float s_in[8 * 10 * 34];   // 2720
    __shared__ float s_w[8 * 9 * 2 * 20]; // 2880

    const int tid = threadIdx.x;
    const int tx = tid & 31;
    const int q = tid >> 5;
    const int ty = q & 3;
    const int oh = q >> 2;
    const int x0 = blockIdx.x * 32, y0 = blockIdx.y * 8;
    const int b = blockIdx.z;

    ull acc[2][9];
#pragma unroll
    for (int p = 0; p < 2; p++)
#pragma unroll
        for (int j = 0; j < 9; j++) acc[p][j] = 0ull;

#pragma unroll 1
    for (int chunk = 0; chunk < 8; chunk++) {
        const float* base = wr + ((size_t)(b * Cc + chunk * 8)) * HW;
        for (int i = tid; i < 2720; i += 256) {
            int c = i / 340, r = i % 340;
            int iy = r / 34, ix = r % 34;
            int gy = y0 - 1 + iy, gx = x0 - 1 + ix;
            float v = 0.f;
            if (gy >= 0 && gy < Hc && gx >= 0 && gx < Wc)
                v = base[(size_t)c * HW + gy * Wc + gx];
            s_in[i] = v;
        }
        for (int i = tid; i < 2880; i += 256) {
            int o = i % 20;
            int rr = i / 20;
            int h = rr & 1;
            int ck = rr >> 1;
            int k = ck % 9, c = ck / 9;
            s_w[i] = (o < 18) ? mw[((h * 18 + o) * 64 + chunk * 8 + c) * 9 + k] : 0.f;
        }
        __syncthreads();

#pragma unroll 2
        for (int c = 0; c < 8; c++) {
#pragma unroll
            for (int t = 0; t < 9; t++) {
                const int kh = t / 3, kw = t % 3;
                const float* wrow = &s_w[((c * 9 + t) * 2 + oh) * 20];
                ulonglong2 l0 = *(const ulonglong2*)(wrow);
                ulonglong2 l1 = *(const ulonglong2*)(wrow + 4);
                ulonglong2 l2 = *(const ulonglong2*)(wrow + 8);
                ulonglong2 l3 = *(const ulonglong2*)(wrow + 12);
                ull w8 = *(const ull*)(wrow + 16);
#pragma unroll
                for (int p = 0; p < 2; p++) {
                    float v = s_in[c * 340 + (ty + p * 4 + kh) * 34 + tx + kw];
                    ull vv = pack2(v, v);
                    acc[p][0] = ffma2(vv, l0.x, acc[p][0]);
                    acc[p][1] = ffma2(vv, l0.y, acc[p][1]);
                    acc[p][2] = ffma2(vv, l1.x, acc[p][2]);
                    acc[p][3] = ffma2(vv, l1.y, acc[p][3]);
                    acc[p][4] = ffma2(vv, l2.x, acc[p][4]);
                    acc[p][5] = ffma2(vv, l2.y, acc[p][5]);
                    acc[p][6] = ffma2(vv, l3.x, acc[p][6]);
                    acc[p][7] = ffma2(vv, l3.y, acc[p][7]);
                    acc[p][8] = ffma2(vv, w8,  acc[p][8]);
                }
            }
        }
        __syncthreads();
    }

    const int x = x0 + tx;
#pragma unroll
    for (int p = 0; p < 2; p++) {
        int y = y0 + ty + p * 4;
#pragma unroll
        for (int j = 0; j < 9; j++) {
            float2 f = unpack2(acc[p][j]);
            int o0 = oh * 18 + 2 * j, o1 = o0 + 1;
            float v0 = 2.f * sigmoidf_(f.x + mb[o0]);
            float v1 = 2.f * sigmoidf_(f.y + mb[o1]);
            modout[((size_t)(b * 36 + o0) * Hc + y) * Wc + x] = v0;
            modout[((size_t)(b * 36 + o1) * Hc + y) * Wc + x] = v1;
        }
    }
}

// ---------------------------------------------------------------------------
// Kernel 3: FUSED gather + GEMM.
// Block = 256 contiguous pixels. Per (g,k) iter: each thread bilinear-gathers
// its pixel's 16 group channels (NHWC, 4x4 LDG.128) into s_val[buf][c][256];
// weights prefetched via cp.async into s_wk[buf]. GEMM: 8px x 8o FFMA2.
// Double-buffered, one __syncthreads per iter.
// ---------------------------------------------------------------------------
__global__ __launch_bounds__(256, 2) void deform_fused_kernel(
    const float* __restrict__ nhwc,
    const float* __restrict__ off,
    const float* __restrict__ mod,
    const float* __restrict__ gwt,
    float* __restrict__ out_x)
{
    __shared__ float s_val[2][16 * 256];
    __shared__ float s_wk[2][16 * 64];

    const int tid = threadIdx.x;
    const int tpx = tid & 31;
    const int to = tid >> 5;
    const size_t col0 = (size_t)blockIdx.x * 256;
    const int b = blockIdx.x / (HW / 256);
    const size_t p0 = col0 - (size_t)b * HW;

    const int pl = (int)p0 + tid;           // local pixel in [0,HW)
    const int yy = pl / Wc, xx = pl % Wc;
    const float* nb = nhwc + (size_t)b * HW * 64;

    auto gather = [&](int i) {
        const int buf = i & 1;
        const int g = i / 9, k = i % 9;
        const int kh = k / 3, kw = k % 3;
        float oy = off[((size_t)(b * 72 + g * 18 + 2 * k)) * HW + pl];
        float ox = off[((size_t)(b * 72 + g * 18 + 2 * k + 1)) * HW + pl];
        float m  = mod[((size_t)(b * 36 + g * 9 + k)) * HW + pl];

        float py = oy + (float)kh + (float)(yy - 1);
        float px = ox + (float)kw + (float)(xx - 1);
        float fy = floorf(py), fx = floorf(px);
        float ly = py - fy, lx = px - fx;
        int iy0 = (int)fy, ix0 = (int)fx;
        int iy1 = iy0 + 1, ix1 = ix0 + 1;

        float vy0 = (iy0 >= 0 && iy0 < Hc) ? 1.f : 0.f;
        float vy1 = (iy1 >= 0 && iy1 < Hc) ? 1.f : 0.f;
        float vx0 = (ix0 >= 0 && ix0 < Wc) ? 1.f : 0.f;
        float vx1 = (ix1 >= 0 && ix1 < Wc) ? 1.f : 0.f;

        int cy0 = min(max(iy0, 0), Hc - 1), cy1 = min(max(iy1, 0), Hc - 1);
        int cx0 = min(max(ix0, 0), Wc - 1), cx1 = min(max(ix1, 0), Wc - 1);

        ull w00 = pack2((1.f - ly) * (1.f - lx) * m * vy0 * vx0,
                        (1.f - ly) * (1.f - lx) * m * vy0 * vx0);
        ull w01 = pack2((1.f - ly) * lx * m * vy0 * vx1,
                        (1.f - ly) * lx * m * vy0 * vx1);
        ull w10 = pack2(ly * (1.f - lx) * m * vy1 * vx0,
                        ly * (1.f - lx) * m * vy1 * vx0);
        ull w11 = pack2(ly * lx * m * vy1 * vx1,
                        ly * lx * m * vy1 * vx1);

        const float4* p00 = (const float4*)(nb + ((size_t)(cy0 * Wc + cx0)) * 64 + g * 16);
        const float4* p01 = (const float4*)(nb + ((size_t)(cy0 * Wc + cx1)) * 64 + g * 16);
        const float4* p10 = (const float4*)(nb + ((size_t)(cy1 * Wc + cx0)) * 64 + g * 16);
        const float4* p11 = (const float4*)(nb + ((size_t)(cy1 * Wc + cx1)) * 64 + g * 16);

#pragma unroll
        for (int q = 0; q < 4; q++) {
            ulonglong2 a00 = ((const ulonglong2*)p00)[q];
            ulonglong2 a01 = ((const ulonglong2*)p01)[q];
            ulonglong2 a10 = ((const ulonglong2*)p10)[q];
            ulonglong2 a11 = ((const ulonglong2*)p11)[q];
            ull r0 = ffma2(a00.x, w00, 0ull);
            ull r1 = ffma2(a00.y, w00, 0ull);
            r0 = ffma2(a01.x, w01, r0);
            r1 = ffma2(a01.y, w01, r1);
            r0 = ffma2(a10.x, w10, r0);
            r1 = ffma2(a10.y, w10, r1);
            r0 = ffma2(a11.x, w11, r0);
            r1 = ffma2(a11.y, w11, r1);
            float2 f0 = unpack2(r0), f1 = unpack2(r1);
            s_val[buf][(q * 4 + 0) * 256 + tid] = f0.x;
            s_val[buf][(q * 4 + 1) * 256 + tid] = f0.y;
            s_val[buf][(q * 4 + 2) * 256 + tid] = f1.x;
            s_val[buf][(q * 4 + 3) * 256 + tid] = f1.y;
        }
    };

    auto stage_w = [&](int i) {
        int flat = tid * 4;
        int c = flat >> 6, o = flat & 63;
        cp_async16(&s_wk[i & 1][c * 64 + o], &gwt[(i * 16 + c) * 64 + o]);
        asm volatile("cp.async.commit_group;" ::: "memory");
    };

    ull acc[8][4];
#pragma unroll
    for (int p = 0; p < 8; p++)
#pragma unroll
        for (int j = 0; j < 4; j++) acc[p][j] = 0ull;

    stage_w(0);
    gather(0);

#pragma unroll 1
    for (int i = 0; i < 36; i++) {
        asm volatile("cp.async.wait_group 0;" ::: "memory");
        __syncthreads();
        if (i < 35) { stage_w(i + 1); gather(i + 1); }

        const float* vb_ = s_val[i & 1];
        const float* wb_ = s_wk[i & 1];
#pragma unroll
        for (int c = 0; c < 16; c++) {
            float4 va  = *(const float4*)&vb_[c * 256 + tpx * 4];
            float4 vbv = *(const float4*)&vb_[c * 256 + 128 + tpx * 4];
            ulonglong2 wA = *(const ulonglong2*)&wb_[c * 64 + to * 4];
            ulonglong2 wB = *(const ulonglong2*)&wb_[c * 64 + 32 + to * 4];
            ull vv;
            vv = pack2(va.x, va.x);
            acc[0][0] = ffma2(vv, wA.x, acc[0][0]); acc[0][1] = ffma2(vv, wA.y, acc[0][1]);
            acc[0][2] = ffma2(vv, wB.x, acc[0][2]); acc[0][3] = ffma2(vv, wB.y, acc[0][3]);
            vv = pack2(va.y, va.y);
            acc[1][0] = ffma2(vv, wA.x, acc[1][0]); acc[1][1] = ffma2(vv, wA.y, acc[1][1]);
            acc[1][2] = ffma2(vv, wB.x, acc[1][2]); acc[1][3] = ffma2(vv, wB.y, acc[1][3]);
            vv = pack2(va.z, va.z);
            acc[2][0] = ffma2(vv, wA.x, acc[2][0]); acc[2][1] = ffma2(vv, wA.y, acc[2][1]);
            acc[2][2] = ffma2(vv, wB.x, acc[2][2]); acc[2][3] = ffma2(vv, wB.y, acc[2][3]);
            vv = pack2(va.w, va.w);
            acc[3][0] = ffma2(vv, wA.x, acc[3][0]); acc[3][1] = ffma2(vv, wA.y, acc[3][1]);
            acc[3][2] = ffma2(vv, wB.x, acc[3][2]); acc[3][3] = ffma2(vv, wB.y, acc[3][3]);
            vv = pack2(vbv.x, vbv.x);
            acc[4][0] = ffma2(vv, wA.x, acc[4][0]); acc[4][1] = ffma2(vv, wA.y, acc[4][1]);
            acc[4][2] = ffma2(vv, wB.x, acc[4][2]); acc[4][3] = ffma2(vv, wB.y, acc[4][3]);
            vv = pack2(vbv.y, vbv.y);
            acc[5][0] = ffma2(vv, wA.x, acc[5][0]); acc[5][1] = ffma2(vv, wA.y, acc[5][1]);
            acc[5][2] = ffma2(vv, wB.x, acc[5][2]); acc[5][3] = ffma2(vv, wB.y, acc[5][3]);
            vv = pack2(vbv.z, vbv.z);
            acc[6][0] = ffma2(vv, wA.x, acc[6][0]); acc[6][1] = ffma2(vv, wA.y, acc[6][1]);
            acc[6][2] = ffma2(vv, wB.x, acc[6][2]); acc[6][3] = ffma2(vv, wB.y, acc[6][3]);
            vv = pack2(vbv.w, vbv.w);
            acc[7][0] = ffma2(vv, wA.x, acc[7][0]); acc[7][1] = ffma2(vv, wA.y, acc[7][1]);
            acc[7][2] = ffma2(vv, wB.x, acc[7][2]); acc[7][3] = ffma2(vv, wB.y, acc[7][3]);
        }
    }

    // Epilogue: pixels contiguous along p0.
#pragma unroll
    for (int qj = 0; qj < 4; qj++) {
        int o = (qj < 2) ? (to * 4 + 2 * qj) : (32 + to * 4 + 2 * (qj - 2));
        float2 f0 = unpack2(acc[0][qj]);
        float2 f1 = unpack2(acc[1][qj]);
        float2 f2 = unpack2(acc[2][qj]);
        float2 f3 = unpack2(acc[3][qj]);
        float4 lo = make_float4(f0.x, f1.x, f2.x, f3.x);
        float4 hi = make_float4(f0.y, f1.y, f2.y, f3.y);
        *(float4*)&out_x[((size_t)(b * Cc + o)) * HW + p0 + tpx * 4] = lo;
        *(float4*)&out_x[((size_t)(b * Cc + o + 1)) * HW + p0 + tpx * 4] = hi;
        float2 g0 = unpack2(acc[4][qj]);
        float2 g1 = unpack2(acc[5][qj]);
        float2 g2 = unpack2(acc[6][qj]);
        float2 g3 = unpack2(acc[7][qj]);
        float4 lo2 = make_float4(g0.x, g1.x, g2.x, g3.x);
        float4 hi2 = make_float4(g0.y, g1.y, g2.y, g3.y);
        *(float4*)&out_x[((size_t)(b * Cc + o)) * HW + p0 + 128 + tpx * 4] = lo2;
        *(float4*)&out_x[((size_t)(b * Cc + o + 1)) * HW + p0 + 128 + tpx * 4] = hi2;
    }
}

// ---------------------------------------------------------------------------
extern "C" void kernel_launch(void* const* d_in, const int* in_sizes, int n_in,
                              void* d_out, int out_size)
{
    const float* warp_ref = (const float*)d_in[0];
    const float* source   = (const float*)d_in[1];
    const float* offset_w = (const float*)d_in[2];
    const float* offset_b = (const float*)d_in[3];
    const float* mod_w    = (const float*)d_in[4];
    const float* mod_b    = (const float*)d_in[5];
    const float* reg_w    = (const float*)d_in[6];

    float* out_x   = (float*)d_out;             // [B,64,H,W]
    float* out_off = (float*)d_out + X_ELEMS;   // [B,72,H,W]

    float *mod_scratch, *wt_scratch, *nhwc_scratch;
    cudaGetSymbolAddress((void**)&mod_scratch, g_modulator);
    cudaGetSymbolAddress((void**)&wt_scratch, g_wt);
    cudaGetSymbolAddress((void**)&nhwc_scratch, g_nhwc);

    dim3 blk(256);
    wt_transform_kernel<<<144, blk>>>(reg_w, wt_scratch);
    nhwc_kernel<<<dim3(HW / 32, 2, Bc), blk>>>(warp_ref, nhwc_scratch);
    offset_conv_kernel<<<dim3(6, 12, 8), blk>>>(warp_ref, source, offset_w, offset_b, out_off);
    mod_conv_kernel<<<dim3(6, 24, 2), blk>>>(warp_ref, mod_w, mod_b, mod_scratch);
    deform_fused_kernel<<<dim3(Nsz / 256), blk>>>(nhwc_scratch, out_off, mod_scratch, wt_scratch, out_x);
}

// round 6
// speedup vs baseline: 1.6677x; 1.0096x over previous
#include <cuda_runtime.h>
#include <math.h>
#include <stdint.h>

#define Bc   2
#define Cc   64
#define Hc   192
#define Wc   192
#define Gc   4
#define Cgc  16
#define HW   (Hc*Wc)
#define Nsz  (Bc*HW)          // 73728 pixels total

#define X_ELEMS   ((size_t)Bc*Cc*HW)
#define VPAD 516              // s_val row pitch (floats): %4==0 for LDS.128 align
typedef unsigned long long ull;

// Scratch (no allocations allowed)
__device__ float g_modulator[(size_t)Bc*36*HW];
__device__ float g_wt[4*9*16*64];               // [ (g*9+k)*16+c ][ o ]
__device__ float g_gsplit[(size_t)Bc*Gc*HW*16]; // [b*4+g][p][16ch]

// ---- helpers --------------------------------------------------------------
__device__ __forceinline__ ull ffma2(ull a, ull b, ull c) {
    ull d;
    asm("fma.rn.f32x2 %0, %1, %2, %3;" : "=l"(d) : "l"(a), "l"(b), "l"(c));
    return d;
}
__device__ __forceinline__ ull pack2(float lo, float hi) {
    ull r;
    asm("mov.b64 %0, {%1, %2};" : "=l"(r) : "f"(lo), "f"(hi));
    return r;
}
__device__ __forceinline__ float2 unpack2(ull v) {
    float2 f;
    asm("mov.b64 {%0, %1}, %2;" : "=f"(f.x), "=f"(f.y) : "l"(v));
    return f;
}
__device__ __forceinline__ float sigmoidf_(float v) {
    return 1.f / (1.f + expf(-v));
}
__device__ __forceinline__ void cp_async16(void* smem, const void* g) {
    uint32_t s = (uint32_t)__cvta_generic_to_shared(smem);
    asm volatile("cp.async.cg.shared.global [%0], [%1], 16;" :: "r"(s), "l"(g));
}

// ---------------------------------------------------------------------------
// Kernel 0a: weight transform  reg_w[o][ic][kh][kw] -> g_wt[(g*9+k)*16+c][o]
// ---------------------------------------------------------------------------
__global__ void wt_transform_kernel(const float* __restrict__ w, float* __restrict__ wt)
{
    int i = blockIdx.x * 256 + threadIdx.x;   // 36864 total
    int o = i & 63;
    int r = i >> 6;
    int c = r & 15;
    int r2 = r >> 4;
    int k = r2 % 9, g = r2 / 9;
    wt[i] = w[(o * 64 + g * 16 + c) * 9 + k];
}

// ---------------------------------------------------------------------------
// Kernel 0b: NCHW -> group-split transpose: [b][64][HW] -> [b*4+g][HW][16]
// ---------------------------------------------------------------------------
__global__ __launch_bounds__(256) void gsplit_kernel(
    const float* __restrict__ in, float* __restrict__ outp)
{
    __shared__ float t[32][33];
    const int tx = threadIdx.x & 31, ty = threadIdx.x >> 5;
    const int p0 = blockIdx.x * 32;
    const int c0 = blockIdx.y * 32;
    const int b  = blockIdx.z;
#pragma unroll
    for (int j = 0; j < 4; j++) {
        int c = c0 + ty + j * 8;
        t[ty + j * 8][tx] = in[((size_t)(b * Cc + c)) * HW + p0 + tx];
    }
    __syncthreads();
#pragma unroll
    for (int j = 0; j < 4; j++) {
        int p = p0 + ty + j * 8;
        int c = c0 + tx;
        int g = c >> 4, ci = c & 15;
        outp[((size_t)(b * 4 + g) * HW + p) * 16 + ci] = t[tx][ty + j * 8];
    }
}

// ---------------------------------------------------------------------------
// Kernel 1: offset conv (unchanged)
// ---------------------------------------------------------------------------
__global__ __launch_bounds__(256) void offset_conv_kernel(
    const float* __restrict__ wr, const float* __restrict__ src,
    const float* __restrict__ ow, const float* __restrict__ ob,
    float* __restrict__ out_off)
{
    __shared__ float s_in[8 * 18 * 34];
    __shared__ float s_w[8 * 9 * 20];

    const int tid = threadIdx.x;
    const int tx = tid & 31, ty = tid >> 5;
    const int x0 = blockIdx.x * 32, y0 = blockIdx.y * 16;
    const int bz = blockIdx.z;
    const int g = bz & 3, b = bz >> 2;

    ull acc[2][9];
#pragma unroll
    for (int p = 0; p < 2; p++)
#pragma unroll
        for (int j = 0; j < 9; j++) acc[p][j] = 0ull;

#pragma unroll 1
    for (int chunk = 0; chunk < 4; chunk++) {
        const float* base = (chunk < 2 ? wr : src)
                          + ((size_t)(b * Cc + g * Cgc + (chunk & 1) * 8)) * HW;
        for (int i = tid; i < 4896; i += 256) {
            int c = i / 612, r = i % 612;
            int iy = r / 34, ix = r % 34;
            int gy = y0 - 1 + iy, gx = x0 - 1 + ix;
            float v = 0.f;
            if (gy >= 0 && gy < Hc && gx >= 0 && gx < Wc)
                v = base[(size_t)c * HW + gy * Wc + gx];
            s_in[i] = v;
        }
        for (int i = tid; i < 1440; i += 256) {
            int o = i % 20;
            int ck = i / 20;
            int k = ck % 9, c = ck / 9;
            s_w[i] = (o < 18) ? ow[(o * 32 + chunk * 8 + c) * 9 + k] : 0.f;
        }
        __syncthreads();

#pragma unroll 2
        for (int c = 0; c < 8; c++) {
#pragma unroll
            for (int t = 0; t < 9; t++) {
                const int kh = t / 3, kw = t % 3;
                const float* wrow = &s_w[(c * 9 + t) * 20];
                ulonglong2 l0 = *(const ulonglong2*)(wrow);
                ulonglong2 l1 = *(const ulonglong2*)(wrow + 4);
                ulonglong2 l2 = *(const ulonglong2*)(wrow + 8);
                ulonglong2 l3 = *(const ulonglong2*)(wrow + 12);
                ull w8 = *(const ull*)(wrow + 16);
#pragma unroll
                for (int p = 0; p < 2; p++) {
                    float v = s_in[c * 612 + (ty + p * 8 + kh) * 34 + tx + kw];
                    ull vv = pack2(v, v);
                    acc[p][0] = ffma2(vv, l0.x, acc[p][0]);
                    acc[p][1] = ffma2(vv, l0.y, acc[p][1]);
                    acc[p][2] = ffma2(vv, l1.x, acc[p][2]);
                    acc[p][3] = ffma2(vv, l1.y, acc[p][3]);
                    acc[p][4] = ffma2(vv, l2.x, acc[p][4]);
                    acc[p][5] = ffma2(vv, l2.y, acc[p][5]);
                    acc[p][6] = ffma2(vv, l3.x, acc[p][6]);
                    acc[p][7] = ffma2(vv, l3.y, acc[p][7]);
                    acc[p][8] = ffma2(vv, w8,  acc[p][8]);
                }
            }
        }
        __syncthreads();
    }

    const int x = x0 + tx;
#pragma unroll
    for (int p = 0; p < 2; p++) {
        int y = y0 + ty + p * 8;
#pragma unroll
        for (int j = 0; j < 9; j++) {
            float2 f = unpack2(acc[p][j]);
            int o0 = 2 * j, o1 = 2 * j + 1;
            float v0 = 100.f * sigmoidf_(f.x + ob[o0]) - 50.f;
            float v1 = 100.f * sigmoidf_(f.y + ob[o1]) - 50.f;
            out_off[((size_t)(b * 72 + g * 18 + o0) * Hc + y) * Wc + x] = v0;
            out_off[((size_t)(b * 72 + g * 18 + o1) * Hc + y) * Wc + x] = v1;
        }
    }
}

// ---------------------------------------------------------------------------
// Kernel 2: modulator conv (unchanged)
// ---------------------------------------------------------------------------
__global__ __launch_bounds__(256) void mod_conv_kernel(
    const float* __restrict__ wr,
    const float* __restrict__ mw, const float* __restrict__ mb,
    float* __restrict__ modout)
{
    __shared__ float s_in[8 * 10 * 34];
    __shared__ float s_w[8 * 9 * 2 * 20];

    const int tid = threadIdx.x;
    const int tx = tid & 31;
    const int q = tid >> 5;
    const int ty = q & 3;
    const int oh = q >> 2;
    const int x0 = blockIdx.x * 32, y0 = blockIdx.y * 8;
    const int b = blockIdx.z;

    ull acc[2][9];
#pragma unroll
    for (int p = 0; p < 2; p++)
#pragma unroll
        for (int j = 0; j < 9; j++) acc[p][j] = 0ull;

#pragma unroll 1
    for (int chunk = 0; chunk < 8; chunk++) {
        const float* base = wr + ((size_t)(b * Cc + chunk * 8)) * HW;
        for (int i = tid; i < 2720; i += 256) {
            int c = i / 340, r = i % 340;
            int iy = r / 34, ix = r % 34;
            int gy = y0 - 1 + iy, gx = x0 - 1 + ix;
            float v = 0.f;
            if (gy >= 0 && gy < Hc && gx >= 0 && gx < Wc)
                v = base[(size_t)c * HW + gy * Wc + gx];
            s_in[i] = v;
        }
        for (int i = tid; i < 2880; i += 256) {
            int o = i % 20;
            int rr = i / 20;
            int h = rr & 1;
            int ck = rr >> 1;
            int k = ck % 9, c = ck / 9;
            s_w[i] = (o < 18) ? mw[((h * 18 + o) * 64 + chunk * 8 + c) * 9 + k] : 0.f;
        }
        __syncthreads();

#pragma unroll 2
        for (int c = 0; c < 8; c++) {
#pragma unroll
            for (int t = 0; t < 9; t++) {
                const int kh = t / 3, kw = t % 3;
                const float* wrow = &s_w[((c * 9 + t) * 2 + oh) * 20];
                ulonglong2 l0 = *(const ulonglong2*)(wrow);
                ulonglong2 l1 = *(const ulonglong2*)(wrow + 4);
                ulonglong2 l2 = *(const ulonglong2*)(wrow + 8);
                ulonglong2 l3 = *(const ulonglong2*)(wrow + 12);
                ull w8 = *(const ull*)(wrow + 16);
#pragma unroll
                for (int p = 0; p < 2; p++) {
                    float v = s_in[c * 340 + (ty + p * 4 + kh) * 34 + tx + kw];
                    ull vv = pack2(v, v);
                    acc[p][0] = ffma2(vv, l0.x, acc[p][0]);
                    acc[p][1] = ffma2(vv, l0.y, acc[p][1]);
                    acc[p][2] = ffma2(vv, l1.x, acc[p][2]);
                    acc[p][3] = ffma2(vv, l1.y, acc[p][3]);
                    acc[p][4] = ffma2(vv, l2.x, acc[p][4]);
                    acc[p][5] = ffma2(vv, l2.y, acc[p][5]);
                    acc[p][6] = ffma2(vv, l3.x, acc[p][6]);
                    acc[p][7] = ffma2(vv, l3.y, acc[p][7]);
                    acc[p][8] = ffma2(vv, w8,  acc[p][8]);
                }
            }
        }
        __syncthreads();
    }

    const int x = x0 + tx;
#pragma unroll
    for (int p = 0; p < 2; p++) {
        int y = y0 + ty + p * 4;
#pragma unroll
        for (int j = 0; j < 9; j++) {
            float2 f = unpack2(acc[p][j]);
            int o0 = oh * 18 + 2 * j, o1 = o0 + 1;
            float v0 = 2.f * sigmoidf_(f.x + mb[o0]);
            float v1 = 2.f * sigmoidf_(f.y + mb[o1]);
            modout[((size_t)(b * 36 + o0) * Hc + y) * Wc + x] = v0;
            modout[((size_t)(b * 36 + o1) * Hc + y) * Wc + x] = v1;
        }
    }
}

// ---------------------------------------------------------------------------
// Kernel 3: FUSED deform. Block = 512 px. Cooperative gather: 8 lanes/px
// (half,quarter), row-pair loads from group-split layout (x-adjacent corners
// contiguous), x-combine via shfl.xor(4). GEMM: 8px x 16o FFMA2/thread.
// ---------------------------------------------------------------------------
__global__ __launch_bounds__(256) void deform_fused_kernel(
    const float* __restrict__ gsp,   // [b*4+g][HW][16]
    const float* __restrict__ off,   // [B,72,H,W]
    const float* __restrict__ mod,   // [B,36,H,W]
    const float* __restrict__ gwt,   // [36*16][64]
    float* __restrict__ out_x)
{
    __shared__ float s_val[2][16 * VPAD];
    __shared__ float s_wk[2][16 * 64];

    const int tid = threadIdx.x;
    const int warp = tid >> 5, lane = tid & 31;
    const int sub = lane >> 3;          // px within 4-px step
    const int jj = lane & 7;            // lane within px octet
    const int half = jj >> 2, qq = jj & 3;
    const int blk = blockIdx.x;
    const int b = blk / (HW / 512);
    const int ploc0 = (blk % (HW / 512)) * 512;

    // GEMM mapping: 4 o-groups x 64 px-groups
    const int to = tid >> 6;            // 0..3 (16 outs each)
    const int tpx = tid & 63;           // 8 px each

    const float fhalf = (float)half;

    auto gather = [&](int i) {
        const int buf = i & 1;
        const int g = i / 9, k = i % 9;
        const int kh = k / 3, kw = k % 3;
        const float* gplane = gsp + (size_t)(b * 4 + g) * HW * 16;
        const float* offy = off + (size_t)(b * 72 + g * 18 + 2 * k) * HW + ploc0;
        const float* offx = offy + (size_t)HW;
        const float* modp = mod + (size_t)(b * 36 + g * 9 + k) * HW + ploc0;
        float* sv = s_val[buf];

#pragma unroll 4
        for (int s = 0; s < 16; s++) {
            const int pl = warp * 64 + s * 4 + sub;
            const int p = ploc0 + pl;
            const int yy = p / Wc, xx = p % Wc;
            float oy = __ldg(&offy[pl]);
            float ox = __ldg(&offx[pl]);
            float m  = __ldg(&modp[pl]);

            float py = oy + (float)(kh + yy - 1);
            float pxf = ox + (float)(kw + xx - 1);
            float fy = floorf(py), fx = floorf(pxf);
            float ly = py - fy, lx = pxf - fx;
            int y0 = (int)fy, x0 = (int)fx;

            float vx0 = (x0 >= 0 && x0 < Wc) ? 1.f : 0.f;
            float vx1 = (x0 >= -1 && x0 <= Wc - 2) ? 1.f : 0.f;
            float vy0 = (y0 >= 0 && y0 < Hc) ? 1.f : 0.f;
            float vy1 = (y0 >= -1 && y0 <= Hc - 2) ? 1.f : 0.f;

            int rbx = min(max(x0, 0), Wc - 2);
            int cx0 = min(max(x0, 0), Wc - 1);
            int cx1 = min(max(x0 + 1, 0), Wc - 1);
            float s0 = (float)(cx0 - rbx);
            float s1 = (float)(cx1 - rbx);
            float wx0 = (1.f - lx) * vx0;
            float wx1 = lx * vx1;
            // x-half selector weight for this lane
            float hw = wx0 * (s0 == fhalf ? 1.f : 0.f) + wx1 * (s1 == fhalf ? 1.f : 0.f);

            int ry0 = min(max(y0, 0), Hc - 1);
            int ry1 = min(max(y0 + 1, 0), Hc - 1);
            float a0 = (1.f - ly) * vy0 * m * hw;
            float a1 = ly * vy1 * m * hw;

            const float4* r0p = (const float4*)(gplane + ((size_t)(ry0 * Wc + rbx)) * 16) + jj;
            const float4* r1p = (const float4*)(gplane + ((size_t)(ry1 * Wc + rbx)) * 16) + jj;
            float4 v0 = __ldg(r0p);
            float4 v1 = __ldg(r1p);

            float4 u;
            u.x = v0.x * a0 + v1.x * a1;
            u.y = v0.y * a0 + v1.y * a1;
            u.z = v0.z * a0 + v1.z * a1;
            u.w = v0.w * a0 + v1.w * a1;
            // combine x-halves (octet stride 4)
            u.x += __shfl_xor_sync(0xFFFFFFFFu, u.x, 4);
            u.y += __shfl_xor_sync(0xFFFFFFFFu, u.y, 4);
            u.z += __shfl_xor_sync(0xFFFFFFFFu, u.z, 4);
            u.w += __shfl_xor_sync(0xFFFFFFFFu, u.w, 4);

            if (half == 0) {
                int cb = qq * 4;
                sv[(cb + 0) * VPAD + pl] = u.x;
                sv[(cb + 1) * VPAD + pl] = u.y;
                sv[(cb + 2) * VPAD + pl] = u.z;
                sv[(cb + 3) * VPAD + pl] = u.w;
            }
        }
    };

    auto stage_w = [&](int i) {
        int flat = tid * 4;
        int c = flat >> 6, o = flat & 63;
        cp_async16(&s_wk[i & 1][c * 64 + o], &gwt[(i * 16 + c) * 64 + o]);
        asm volatile("cp.async.commit_group;" ::: "memory");
    };

    ull acc[8][8];
#pragma unroll
    for (int p = 0; p < 8; p++)
#pragma unroll
        for (int j = 0; j < 8; j++) acc[p][j] = 0ull;

    stage_w(0);
    gather(0);

#pragma unroll 1
    for (int i = 0; i < 36; i++) {
        asm volatile("cp.async.wait_group 0;" ::: "memory");
        __syncthreads();
        if (i < 35) { stage_w(i + 1); gather(i + 1); }

        const float* vb_ = s_val[i & 1];
        const float* wb_ = s_wk[i & 1];
#pragma unroll
        for (int c = 0; c < 16; c++) {
            float4 vA = *(const float4*)&vb_[c * VPAD + tpx * 8];
            float4 vB = *(const float4*)&vb_[c * VPAD + tpx * 8 + 4];
            const float* wrow = &wb_[c * 64 + to * 16];
            ulonglong2 w0 = *(const ulonglong2*)(wrow);
            ulonglong2 w1 = *(const ulonglong2*)(wrow + 4);
            ulonglong2 w2 = *(const ulonglong2*)(wrow + 8);
            ulonglong2 w3 = *(const ulonglong2*)(wrow + 12);
            float vv4[8] = {vA.x, vA.y, vA.z, vA.w, vB.x, vB.y, vB.z, vB.w};
#pragma unroll
            for (int p = 0; p < 8; p++) {
                ull vv = pack2(vv4[p], vv4[p]);
                acc[p][0] = ffma2(vv, w0.x, acc[p][0]);
                acc[p][1] = ffma2(vv, w0.y, acc[p][1]);
                acc[p][2] = ffma2(vv, w1.x, acc[p][2]);
                acc[p][3] = ffma2(vv, w1.y, acc[p][3]);
                acc[p][4] = ffma2(vv, w2.x, acc[p][4]);
                acc[p][5] = ffma2(vv, w2.y, acc[p][5]);
                acc[p][6] = ffma2(vv, w3.x, acc[p][6]);
                acc[p][7] = ffma2(vv, w3.y, acc[p][7]);
            }
        }
    }

    // Epilogue: thread covers px [tpx*8, tpx*8+8), outs [to*16, to*16+16)
    const size_t pbase = (size_t)ploc0 + tpx * 8;
#pragma unroll
    for (int j = 0; j < 8; j++) {
        int o = to * 16 + 2 * j;
        float2 f0 = unpack2(acc[0][j]);
        float2 f1 = unpack2(acc[1][j]);
        float2 f2 = unpack2(acc[2][j]);
        float2 f3 = unpack2(acc[3][j]);
        float2 f4 = unpack2(acc[4][j]);
        float2 f5 = unpack2(acc[5][j]);
        float2 f6 = unpack2(acc[6][j]);
        float2 f7 = unpack2(acc[7][j]);
        float* po0 = &out_x[((size_t)(b * Cc + o)) * HW + pbase];
        float* po1 = &out_x[((size_t)(b * Cc + o + 1)) * HW + pbase];
        *(float4*)(po0)     = make_float4(f0.x, f1.x, f2.x, f3.x);
        *(float4*)(po0 + 4) = make_float4(f4.x, f5.x, f6.x, f7.x);
        *(float4*)(po1)     = make_float4(f0.y, f1.y, f2.y, f3.y);
        *(float4*)(po1 + 4) = make_float4(f4.y, f5.y, f6.y, f7.y);
    }
}

// ---------------------------------------------------------------------------
extern "C" void kernel_launch(void* const* d_in, const int* in_sizes, int n_in,
                              void* d_out, int out_size)
{
    const float* warp_ref = (const float*)d_in[0];
    const float* source   = (const float*)d_in[1];
    const float* offset_w = (const float*)d_in[2];
    const float* offset_b = (const float*)d_in[3];
    const float* mod_w    = (const float*)d_in[4];
    const float* mod_b    = (const float*)d_in[5];
    const float* reg_w    = (const float*)d_in[6];

    float* out_x   = (float*)d_out;             // [B,64,H,W]
    float* out_off = (float*)d_out + X_ELEMS;   // [B,72,H,W]

    float *mod_scratch, *wt_scratch, *gsp_scratch;
    cudaGetSymbolAddress((void**)&mod_scratch, g_modulator);
    cudaGetSymbolAddress((void**)&wt_scratch, g_wt);
    cudaGetSymbolAddress((void**)&gsp_scratch, g_gsplit);

    dim3 blk(256);
    wt_transform_kernel<<<144, blk>>>(reg_w, wt_scratch);
    gsplit_kernel<<<dim3(HW / 32, 2, Bc), blk>>>(warp_ref, gsp_scratch);
    offset_conv_kernel<<<dim3(6, 12, 8), blk>>>(warp_ref, source, offset_w, offset_b, out_off);
    mod_conv_kernel<<<dim3(6, 24, 2), blk>>>(warp_ref, mod_w, mod_b, mod_scratch);
    deform_fused_kernel<<<dim3(Nsz / 512), blk>>>(gsp_scratch, out_off, mod_scratch, wt_scratch, out_x);
}